// round 12
// baseline (speedup 1.0000x reference)
#include <cuda_runtime.h>
#include <cuda_bf16.h>
#include <stdint.h>
#include <math.h>

#if defined(__CUDA_ARCH_FEAT_SM103_ALL) || defined(__CUDA_ARCH_FEAT_SM100_ALL) || defined(__CUDA_ARCH_FEAT_SM101_ALL)
#define HAS_TC 1
#else
#define HAS_TC 0
#endif

#define BB 32768
#define LN_EPS 1e-5f
#define SC_ATT 0.125f
#define OFF_SIGMA (3*BB)
#define OFF_OUT (OFF_SIGMA+BB)
#define OFF_ATTN (OFF_OUT+(size_t)BB*512)
#define MMA_GRID 2048

__device__ __nv_bfloat16 g_Bh[88*8192];   // per tile: 4096 hi then 4096 lo
__device__ int g_ok;

extern "C" __global__ void reset_kernel(){ g_ok = 0; }

__device__ __forceinline__ int axAf(int m,int k){return ((k>>5)<<12)|((m>>3)<<8)|((m&7)<<5)|((k&31)^((m&7)<<2));}
__device__ __forceinline__ int axHb(int r,int k){
    int byte=(r&7)*128+k*2; byte^=((byte>>3)&0x70);
    return ((r>>3)<<9)+(byte>>1);
}
__device__ __forceinline__ void sp2b(float v,__nv_bfloat16&h,__nv_bfloat16&l){
    h=__float2bfloat16(v); l=__float2bfloat16(v-(float)h);
}

extern "C" __global__ void prep_kernel(const float* W1,const float* Wq,const float* Wk,const float* Wv,
        const float* Wo,const float* fW1,const float* fW2,const float* cWk,const float* cWv){
    int idx=blockIdx.x*256+threadIdx.x;
    if(idx>=88*4096)return;
    int tile=idx>>12,j=idx&4095,n=j>>6,k=j&63;
    float v;
    if(tile<8) v=W1[(tile*64+k)*64+n];
    else if(tile<56){int t=tile-8,lh=t/3,wch=t%3,li=lh>>2,h=lh&3;
        const float* W=(wch==0)?Wq:((wch==1)?Wk:Wv);
        v=W[li*16384+k*256+h*64+n];}
    else if(tile<72){int t=tile-56,li=t>>2,h=t&3; v=Wo[li*16384+(h*64+k)*64+n];}
    else if(tile<80){int t=tile-72,li=t>>1; v=((t&1)?fW2:fW1)[li*4096+k*64+n];}
    else if(tile<84) v=cWk[k*256+(tile-80)*64+n];
    else v=cWv[k*256+(tile-84)*64+n];
    __nv_bfloat16 h,l; sp2b(v,h,l);
    int ax=axHb(n,k);
    g_Bh[(size_t)tile*8192+ax]=h;
    g_Bh[(size_t)tile*8192+4096+ax]=l;
}

#if HAS_TC
#define NTM 512
#define IDESC 0x8100490u
#define O_XH 0
#define O_XL 4096
#define O_R0 8192
#define O_R1 12288
#define O_R2 16384
#define O_R3 20480
#define O_SP 24576
#define O_QC 25600
#define O_SQI 26624
#define O_CTL 27648
#define SMEMF 27664

__device__ __forceinline__ uint32_t s2u(const void* p){
    uint32_t a; asm("{.reg .u64 t; cvta.to.shared.u64 t,%1; cvt.u32.u64 %0,t;}":"=r"(a):"l"(p)); return a;
}
__device__ __forceinline__ uint32_t elect1(){
    uint32_t r; asm volatile("{.reg .pred p; elect.sync _|p,0xFFFFFFFF; selp.b32 %0,1,0,p;}":"=r"(r)); return r;
}
__device__ __forceinline__ uint64_t sdesc(uint32_t a){
    const uint64_t b=(uint64_t(2)<<61)|(uint64_t(1)<<46)|(uint64_t(64)<<32)|(uint64_t(1)<<16);
    return b|((a>>4)&0x3FFFu);
}
__device__ __forceinline__ void mma1(uint32_t d,uint64_t ad,uint64_t bd,uint32_t en){
    asm volatile("{.reg .pred p; setp.ne.u32 p,%4,0;\n\t"
        "tcgen05.mma.cta_group::1.kind::f16 [%0],%1,%2,%3,{%5,%5,%5,%5},p;}"
        ::"r"(d),"l"(ad),"l"(bd),"r"(IDESC),"r"(en),"r"(0u):"memory");
}
__device__ __forceinline__ void mma_k64b(uint32_t d,uint32_t a_s,uint32_t b_s,bool acc){
    uint64_t ad=sdesc(a_s),bd=sdesc(b_s);
#pragma unroll
    for(int s=0;s<4;++s)
        mma1(d,ad+(uint32_t)(s*2),bd+(uint32_t)(s*2),(acc||s>0)?1u:0u);
}
__device__ __forceinline__ void mma3b(uint32_t d,uint32_t ah,uint32_t al,uint32_t bh,uint32_t bl,bool acc){
    mma_k64b(d,ah,bh,acc);
    mma_k64b(d,al,bh,true);
    mma_k64b(d,ah,bl,true);
}
#define TCOMMIT(mb) asm volatile("tcgen05.commit.cta_group::1.mbarrier::arrive::one.shared::cluster.b64 [%0];"::"r"(mb):"memory")
#define FPA() asm volatile("fence.proxy.async.shared::cta;":::"memory")
#define TFA() asm volatile("tcgen05.fence::after_thread_sync;":::"memory")
#define TFB() asm volatile("tcgen05.fence::before_thread_sync;":::"memory")

__device__ __forceinline__ bool mb_poll(uint32_t mb,uint32_t par){
    for(int i=0;i<40000;++i){
        uint32_t d;
        asm volatile("{.reg .pred P; mbarrier.try_wait.parity.acquire.cta.shared::cta.b64 P,[%1],%2,0x989680; selp.b32 %0,1,0,P;}"
            :"=r"(d):"r"(mb),"r"(par):"memory");
        if(d) return true;
    }
    return false;
}
__device__ __forceinline__ void ldtm16(uint32_t t,float* f){
    uint32_t r[16];
    asm volatile("tcgen05.ld.sync.aligned.32x32b.x16.b32 {%0,%1,%2,%3,%4,%5,%6,%7,%8,%9,%10,%11,%12,%13,%14,%15},[%16];"
        :"=r"(r[0]),"=r"(r[1]),"=r"(r[2]),"=r"(r[3]),"=r"(r[4]),"=r"(r[5]),"=r"(r[6]),"=r"(r[7]),
         "=r"(r[8]),"=r"(r[9]),"=r"(r[10]),"=r"(r[11]),"=r"(r[12]),"=r"(r[13]),"=r"(r[14]),"=r"(r[15])
        :"r"(t));
    asm volatile("tcgen05.wait::ld.sync.aligned;":::"memory");
#pragma unroll
    for(int i=0;i<16;++i) f[i]=__uint_as_float(r[i]);
}
__device__ __forceinline__ void ldtm32(uint32_t t,float* f){
    uint32_t r[32];
    asm volatile("tcgen05.ld.sync.aligned.32x32b.x32.b32 "
        "{%0,%1,%2,%3,%4,%5,%6,%7,%8,%9,%10,%11,%12,%13,%14,%15,"
        "%16,%17,%18,%19,%20,%21,%22,%23,%24,%25,%26,%27,%28,%29,%30,%31},[%32];"
        :"=r"(r[0]),"=r"(r[1]),"=r"(r[2]),"=r"(r[3]),"=r"(r[4]),"=r"(r[5]),"=r"(r[6]),"=r"(r[7]),
         "=r"(r[8]),"=r"(r[9]),"=r"(r[10]),"=r"(r[11]),"=r"(r[12]),"=r"(r[13]),"=r"(r[14]),"=r"(r[15]),
         "=r"(r[16]),"=r"(r[17]),"=r"(r[18]),"=r"(r[19]),"=r"(r[20]),"=r"(r[21]),"=r"(r[22]),"=r"(r[23]),
         "=r"(r[24]),"=r"(r[25]),"=r"(r[26]),"=r"(r[27]),"=r"(r[28]),"=r"(r[29]),"=r"(r[30]),"=r"(r[31])
        :"r"(t));
    asm volatile("tcgen05.wait::ld.sync.aligned;":::"memory");
#pragma unroll
    for(int i=0;i<32;++i) f[i]=__uint_as_float(r[i]);
}
__device__ __forceinline__ void epi_fullf(uint32_t t,const float* bias,float* X,int m_r,int c0){
    float r[16]; ldtm16(t,r);
#pragma unroll
    for(int i=0;i<16;i+=4){
        float4 v=make_float4(r[i]+bias[i],r[i+1]+bias[i+1],r[i+2]+bias[i+2],r[i+3]+bias[i+3]);
        *reinterpret_cast<float4*>(X+axAf(m_r,c0+i))=v;
    }
}
// dual-tile epilogue: warps 0-7 -> tile A, warps 8-15 -> tile B; one x32 load each
__device__ __forceinline__ void epi_dualf(uint32_t tA,uint32_t tB,const float* bA,const float* bB,
        float* dA,float* dB,int wid,int m_r){
    const int grp=wid>>3, cb=((wid>>2)&1)*32;
    uint32_t t=(grp?tB:tA)+cb;
    const float* bias=(grp?bB:bA)+cb;
    float* dst=grp?dB:dA;
    float r[32]; ldtm32(t,r);
#pragma unroll
    for(int i=0;i<32;i+=4){
        float4 v=make_float4(r[i]+bias[i],r[i+1]+bias[i+1],r[i+2]+bias[i+2],r[i+3]+bias[i+3]);
        *reinterpret_cast<float4*>(dst+axAf(m_r,cb+i))=v;
    }
}
__device__ __forceinline__ void epi_splitb(uint32_t t,const float* bias,
        __nv_bfloat16* Hb,__nv_bfloat16* Lb,int m_r,int c0,bool relu){
    float r[16]; ldtm16(t,r);
#pragma unroll
    for(int j=0;j<8;++j){
        float v0=r[2*j]+bias[2*j], v1=r[2*j+1]+bias[2*j+1];
        if(relu){v0=fmaxf(v0,0.f);v1=fmaxf(v1,0.f);}
        __nv_bfloat16 h0,l0,h1,l1;
        sp2b(v0,h0,l0); sp2b(v1,h1,l1);
        int k=c0+2*j;
        int byte=(m_r&7)*128+k*2; byte^=((byte>>3)&0x70);
        int base=((m_r>>3)<<10)+byte;
        __nv_bfloat162 hp; hp.x=h0; hp.y=h1;
        __nv_bfloat162 lp; lp.x=l0; lp.y=l1;
        *reinterpret_cast<__nv_bfloat162*>(reinterpret_cast<char*>(Hb)+base)=hp;
        *reinterpret_cast<__nv_bfloat162*>(reinterpret_cast<char*>(Lb)+base)=lp;
    }
}
__device__ __forceinline__ void cp_f4m(float* d,const float* s,int n4,int tid){
    for(int i=tid;i<n4;i+=NTM) reinterpret_cast<float4*>(d)[i]=reinterpret_cast<const float4*>(s)[i];
}
__device__ __forceinline__ void cp_pair(float* dst,int tile,int tid){
    const float4* s=reinterpret_cast<const float4*>(g_Bh+(size_t)tile*8192);
    for(int i=tid;i<1024;i+=NTM) reinterpret_cast<float4*>(dst)[i]=s[i];
}
__device__ __forceinline__ void cp_slicem(float* d,const float* s,int tid){
    for(int i=tid;i<1024;i+=NTM){int r=i>>4,c=i&15;
        reinterpret_cast<float4*>(d)[i]=reinterpret_cast<const float4*>(s+r*256)[c];}
}
__device__ __forceinline__ void ln_b(const float* Y,__nv_bfloat16* XHb,__nv_bfloat16* XLb,
        const float* g,const float* be,int w,int l){
    float g0=g[l],g1v=g[l+32],e0=be[l],e1v=be[l+32];
#pragma unroll
    for(int i=0;i<8;++i){
        int r=w*8+i;
        int y0=axAf(r,l), y1=axAf(r,l+32);
        int b0i=axHb(r,l), b1i=axHb(r,l+32);
        float v0=Y[y0]+(float)XHb[b0i]+(float)XLb[b0i];
        float v1=Y[y1]+(float)XHb[b1i]+(float)XLb[b1i];
        float s=v0+v1;
#pragma unroll
        for(int o=16;o>=1;o>>=1)s+=__shfl_xor_sync(0xffffffffu,s,o);
        float m=s*(1.f/64.f),d0=v0-m,d1=v1-m,q=d0*d0+d1*d1;
#pragma unroll
        for(int o=16;o>=1;o>>=1)q+=__shfl_xor_sync(0xffffffffu,q,o);
        float inv=rsqrtf(q*(1.f/64.f)+LN_EPS);
        float a=d0*inv*g0+e0, b=d1*inv*g1v+e1v;
        sp2b(a,XHb[b0i],XLb[b0i]);
        sp2b(b,XHb[b1i],XLb[b1i]);
    }
}
#define WAITX do{ \
    if(tid==0){ if(SOK[0] && !mb_poll(mbv[wc&1],(uint32_t)((wc>>1)&1))) SOK[0]=0; } \
    __syncthreads(); \
    wc++; }while(0)
#endif

extern "C" __global__ void __launch_bounds__(512,2)
#if HAS_TC
__cluster_dims__(1,1,1)
#endif
radiance_mma(const float* __restrict__ query,const float* __restrict__ latent,
        const float* __restrict__ b1,const float* __restrict__ bq,const float* __restrict__ bk,
        const float* __restrict__ bv,const float* __restrict__ bo,const float* __restrict__ fb1,
        const float* __restrict__ fb2,const float* __restrict__ g1,const float* __restrict__ be1,
        const float* __restrict__ g2,const float* __restrict__ be2,const float* __restrict__ cWq,
        const float* __restrict__ cbq,const float* __restrict__ cbk,const float* __restrict__ cbv,
        const float* __restrict__ cWo,const float* __restrict__ cbo,const float* __restrict__ Wc,
        const float* __restrict__ bc,const float* __restrict__ Ws,const float* __restrict__ bs,
        float* __restrict__ out){
#if HAS_TC
    extern __shared__ float smem[];
    float* R0f=smem+O_R0; float* R1f=smem+O_R1; float* R2f=smem+O_R2; float* R3f=smem+O_R3;
    __nv_bfloat16* XHb=reinterpret_cast<__nv_bfloat16*>(smem+O_XH);
    __nv_bfloat16* XLb=reinterpret_cast<__nv_bfloat16*>(smem+O_XL);
    float* SP=smem+O_SP; float* QC=smem+O_QC; float* SQI=smem+O_SQI;
    volatile int* SOK=reinterpret_cast<volatile int*>(smem+O_CTL+6);
    const int tid=threadIdx.x,wid=tid>>5,l=tid&31,w=wid;
    const int b0=blockIdx.x*16;
    const int m_r=(wid&3)*32+l, c0=(wid>>2)*16;
    uint32_t sb=s2u(smem), ctl=sb+O_CTL*4;
    uint32_t mbv[2]={ctl+8,ctl+16};
    int cc=0, wc=0; (void)cc;

    if(tid==0){
        asm volatile("mbarrier.init.shared.b64 [%0],1;"::"r"(mbv[0]):"memory");
        asm volatile("mbarrier.init.shared.b64 [%0],1;"::"r"(mbv[1]):"memory");
        SOK[0]=1;
    }
    if(wid==0){
        asm volatile("tcgen05.alloc.cta_group::1.sync.aligned.shared::cta.b32 [%0],%1;"::"r"(ctl),"r"(256u):"memory");
        asm volatile("tcgen05.relinquish_alloc_permit.cta_group::1.sync.aligned;");
    }
    FPA(); __syncthreads();
    uint32_t tb; asm("ld.shared.b32 %0,[%1];":"=r"(tb):"r"(ctl));
    const uint32_t DQ=tb,DK=tb+64,DV=tb+128,DO=tb+192;
    const uint32_t aXH=sb+O_XH*4,aXL=sb+O_XL*4;
    const uint32_t aR0=sb+O_R0*4,aR1=sb+O_R1*4,aR2=sb+O_R2*4,aR3=sb+O_R3*4;
    float* attn_out=out+OFF_ATTN;

    // ======== stage0: X = relu(latent@W1+b1), K=512 in 8 chunks ========
    for(int ch=0;ch<8;++ch){
        if(ch>=2) WAITX;
        __nv_bfloat16* Ah=reinterpret_cast<__nv_bfloat16*>((ch&1)?R2f:R0f);
        __nv_bfloat16* Al=reinterpret_cast<__nv_bfloat16*>((ch&1)?R3f:R1f);
        float* Bp=(ch&1)?(smem+O_XL):(smem+O_XH);
        uint32_t aAh=(ch&1)?aR2:aR0, aAl=(ch&1)?aR3:aR1;
        uint32_t aBp=(ch&1)?aXL:aXH;
        for(int i=tid;i<2048;i+=NTM){
            int m=i>>4,k4=(i&15)<<2;
            float4 v=*reinterpret_cast<const float4*>(latent+(size_t)(b0*8+m)*512+ch*64+k4);
            __nv_bfloat16 h0,l0,h1,l1,h2,l2,h3,l3;
            sp2b(v.x,h0,l0); sp2b(v.y,h1,l1); sp2b(v.z,h2,l2); sp2b(v.w,h3,l3);
            int byte=(m&7)*128+k4*2; byte^=((byte>>3)&0x70);
            int base=((m>>3)<<10)+byte;
            __nv_bfloat162 p01h; p01h.x=h0; p01h.y=h1;
            __nv_bfloat162 p23h; p23h.x=h2; p23h.y=h3;
            __nv_bfloat162 p01l; p01l.x=l0; p01l.y=l1;
            __nv_bfloat162 p23l; p23l.x=l2; p23l.y=l3;
            *reinterpret_cast<__nv_bfloat162*>(reinterpret_cast<char*>(Ah)+base)=p01h;
            *reinterpret_cast<__nv_bfloat162*>(reinterpret_cast<char*>(Ah)+base+4)=p23h;
            *reinterpret_cast<__nv_bfloat162*>(reinterpret_cast<char*>(Al)+base)=p01l;
            *reinterpret_cast<__nv_bfloat162*>(reinterpret_cast<char*>(Al)+base+4)=p23l;
        }
        cp_pair(Bp,ch,tid);
        FPA(); __syncthreads();
        if(wid==0){ TFA();
            if(elect1()){
                mma3b(DQ,aAh,aAl,aBp,aBp+8192,ch>0);
                TCOMMIT(mbv[cc&1]);
            }
        }
        cc++;
    }
    WAITX; WAITX;
    TFA();
    epi_splitb(DQ+c0,b1+c0,XHb,XLb,m_r,c0,true);
    TFB(); FPA(); __syncthreads();

    // ======== 4 transformer layers ========
    for(int li=0;li<4;++li){
        for(int h=0;h<4;++h){
            if(h>0) WAITX;                 // O-mma(h-1)
            int base=8+(li*4+h)*3;
            cp_pair(R0f,base,tid);         // Bq pair
            if(h==0) cp_pair(R1f,base+1,tid);   // Bk pair (h>0: pre-staged)
            cp_pair(R2f,base+2,tid);       // Bv pair
            FPA(); __syncthreads();
            if(wid==0){ TFA();
                if(elect1()){
                    mma3b(DQ,aXH,aXL,aR0,aR0+8192,false);
                    mma3b(DK,aXH,aXL,aR1,aR1+8192,false);
                    mma3b(DV,aXH,aXL,aR2,aR2+8192,false);
                    TCOMMIT(mbv[cc&1]);
                }
            }
            cc++;
            WAITX;
            TFA();
            // dual x32 epilogue: warps 0-7 -> Q (R0R1), warps 8-15 -> K (R2R3)
            epi_dualf(DQ,DK,bq+li*256+h*64,bk+li*256+h*64,R0f,R2f,wid,m_r);
            TFB();
            __syncthreads();
            {   // scores per warp (= batch), fp32
                const int qi=l>>3,kj=l&7;
                float s0=0.f,s1=0.f;
#pragma unroll
                for(int d4=0;d4<64;d4+=4){
                    float4 kv=*reinterpret_cast<const float4*>(R2f+axAf(w*8+kj,d4));
                    float4 q0=*reinterpret_cast<const float4*>(R0f+axAf(w*8+qi,d4));
                    float4 q1=*reinterpret_cast<const float4*>(R0f+axAf(w*8+qi+4,d4));
                    s0+=q0.x*kv.x+q0.y*kv.y+q0.z*kv.z+q0.w*kv.w;
                    s1+=q1.x*kv.x+q1.y*kv.y+q1.z*kv.z+q1.w*kv.w;
                }
                s0*=SC_ATT;s1*=SC_ATT;
                float m0=s0,m1=s1;
#pragma unroll
                for(int o=1;o<8;o<<=1){
                    m0=fmaxf(m0,__shfl_xor_sync(0xffffffffu,m0,o));
                    m1=fmaxf(m1,__shfl_xor_sync(0xffffffffu,m1,o));
                }
                float e0=__expf(s0-m0),e1=__expf(s1-m1),t0=e0,t1=e1;
#pragma unroll
                for(int o=1;o<8;o<<=1){
                    t0+=__shfl_xor_sync(0xffffffffu,t0,o);
                    t1+=__shfl_xor_sync(0xffffffffu,t1,o);
                }
                float p0=e0/t0,p1=e1/t1;
                SP[w*64+l]=p0; SP[w*64+32+l]=p1;
                size_t ab=(size_t)(b0+w)*1024+li*256+h*64;
                attn_out[ab+l]=p0; attn_out[ab+32+l]=p1;
            }
            __syncthreads();               // all warps done with Q (R0R1)
            TFA();
            epi_fullf(DV+c0,bv+li*256+h*64+c0,R0f,m_r,c0);   // V fp32 -> R0R1
            TFB();
            __syncthreads();
            {   // ctx = P@V ; split bf16 pair into R2(hi)/R3(lo) (K dead)
                float a0[8],a1[8];
#pragma unroll
                for(int q2=0;q2<8;++q2){a0[q2]=0.f;a1[q2]=0.f;}
#pragma unroll
                for(int kk=0;kk<8;++kk){
                    float v0=R0f[axAf(w*8+kk,l)],v1=R0f[axAf(w*8+kk,l+32)];
#pragma unroll
                    for(int q2=0;q2<8;++q2){
                        float p=SP[w*64+q2*8+kk];
                        a0[q2]+=p*v0; a1[q2]+=p*v1;
                    }
                }
                __nv_bfloat16* CH=reinterpret_cast<__nv_bfloat16*>(R2f);
                __nv_bfloat16* CL=reinterpret_cast<__nv_bfloat16*>(R3f);
#pragma unroll
                for(int q2=0;q2<8;++q2){
                    int i0=axHb(w*8+q2,l), i1=axHb(w*8+q2,l+32);
                    sp2b(a0[q2],CH[i0],CL[i0]);
                    sp2b(a1[q2],CH[i1],CL[i1]);
                }
            }
            FPA(); __syncthreads();        // ctx visible; V dead
            cp_pair(R0f,56+li*4+h,tid);    // Wo pair
            FPA(); __syncthreads();
            if(wid==0){ TFA();
                if(elect1()){ mma3b(DO,aR2,aR3,aR0,aR0+8192,h>0); TCOMMIT(mbv[cc&1]); }
            }
            cc++;
            // pre-stage next head's Bk into R1 while O-mma is in flight (R1 free: O reads R0,R2,R3)
            if(h<3) cp_pair(R1f,8+(li*4+h+1)*3+1,tid);
        } // heads
        WAITX;
        TFA();
        epi_fullf(DO+c0,bo+li*64+c0,R0f,m_r,c0);    // Y fp32 -> R0R1
        TFB(); __syncthreads();
        ln_b(R0f,XHb,XLb,g1+li*64,be1+li*64,w,l);
        cp_pair(R2f,72+li*2,tid);                   // fW1 pair
        cp_pair(R3f,73+li*2,tid);                   // fW2 pair
        FPA(); __syncthreads();
        if(wid==0){ TFA();
            if(elect1()){ mma3b(DQ,aXH,aXL,aR2,aR2+8192,false); TCOMMIT(mbv[cc&1]); }
        }
        cc++;
        WAITX;
        TFA();
        epi_splitb(DQ+c0,fb1+li*64+c0,
                   reinterpret_cast<__nv_bfloat16*>(R0f),
                   reinterpret_cast<__nv_bfloat16*>(R1f),m_r,c0,true);  // h1 pair
        TFB(); FPA(); __syncthreads();
        if(wid==0){ TFA();
            if(elect1()){ mma3b(DK,aR0,aR1,aR3,aR3+8192,false); TCOMMIT(mbv[cc&1]); }
        }
        cc++;
        WAITX;
        TFA();
        epi_fullf(DK+c0,fb2+li*64+c0,R2f,m_r,c0);   // Y2 fp32 -> R2R3
        TFB(); __syncthreads();
        ln_b(R2f,XHb,XLb,g2+li*64,be2+li*64,w,l);
        FPA(); __syncthreads();
    } // layers

    // ======== cross attention ========
    for(int i=tid;i<1024;i+=NTM) SQI[i]=query[(size_t)(b0+(i>>6))*64+(i&63)];
    float ca0=0.f,ca1=0.f;
    for(int h=0;h<4;++h){
        cp_pair(R0f,80+h,tid);
        cp_pair(R1f,84+h,tid);
        cp_slicem(R2f,cWq+h*64,tid);
        cp_f4m(R3f,cWo+h*4096,1024,tid);
        FPA(); __syncthreads();
        if(wid==0){ TFA();
            if(elect1()){
                mma3b(DQ,aXH,aXL,aR0,aR0+8192,false);   // Kc
                mma3b(DK,aXH,aXL,aR1,aR1+8192,false);   // Vc
                TCOMMIT(mbv[cc&1]);
            }
        }
        cc++;
        for(int c=l;c<64;c+=32){
            float a=0.f;
#pragma unroll 8
            for(int k2=0;k2<64;++k2) a+=SQI[w*64+k2]*R2f[k2*64+c];
            QC[w*64+c]=a+cbq[h*64+c];
        }
        __syncwarp();
        WAITX;
        TFA();
        epi_fullf(DQ+c0,cbk+h*64+c0,R0f,m_r,c0);    // Kc fp32 -> R0R1
        TFB();
        __syncthreads();
        {
            const int j=l>>2,part=l&3;
            float sc=0.f;
#pragma unroll
            for(int d4=part*16;d4<part*16+16;d4+=4){
                float4 kv=*reinterpret_cast<const float4*>(R0f+axAf(w*8+j,d4));
                sc+=QC[w*64+d4]*kv.x+QC[w*64+d4+1]*kv.y+QC[w*64+d4+2]*kv.z+QC[w*64+d4+3]*kv.w;
            }
            sc+=__shfl_xor_sync(0xffffffffu,sc,1);
            sc+=__shfl_xor_sync(0xffffffffu,sc,2);
            sc*=SC_ATT;
            if(part==0) SP[w*64+j]=sc;
        }
        __syncthreads();
        TFA();
        epi_fullf(DK+c0,cbv+h*64+c0,R0f,m_r,c0);    // Vc fp32 -> R0R1
        TFB();
        __syncthreads();
        {
            float mx=-1e30f;
#pragma unroll
            for(int jj=0;jj<8;++jj) mx=fmaxf(mx,SP[w*64+jj]);
            float pe[8],ss=0.f;
#pragma unroll
            for(int jj=0;jj<8;++jj){pe[jj]=__expf(SP[w*64+jj]-mx);ss+=pe[jj];}
            float inv=1.f/ss;
            for(int c=l;c<64;c+=32){
                float a=0.f;
#pragma unroll
                for(int jj=0;jj<8;++jj) a+=pe[jj]*R0f[axAf(w*8+jj,c)];
                QC[w*64+c]=a*inv;
            }
            __syncwarp();
#pragma unroll 8
            for(int k2=0;k2<64;++k2){
                float cv=QC[w*64+k2];
                ca0+=cv*R3f[k2*64+l];
                ca1+=cv*R3f[k2*64+32+l];
            }
        }
        __syncthreads();
    }
    // ======== heads: color, sigma, out ========
    {
        float a0=fmaxf(ca0+cbo[l],0.f),a1=fmaxf(ca1+cbo[l+32],0.f);
#pragma unroll
        for(int cq=0;cq<3;++cq){
            float p=a0*Wc[l*3+cq]+a1*Wc[(l+32)*3+cq];
#pragma unroll
            for(int o=16;o>=1;o>>=1)p+=__shfl_xor_sync(0xffffffffu,p,o);
            if(l==0) out[(size_t)(b0+w)*3+cq]=p+bc[cq];
        }
        float m0=-1e30f,m1=-1e30f;
#pragma unroll
        for(int s2=0;s2<8;++s2){
            int i0=axHb(w*8+s2,l), i1=axHb(w*8+s2,l+32);
            m0=fmaxf(m0,(float)XHb[i0]+(float)XLb[i0]);
            m1=fmaxf(m1,(float)XHb[i1]+(float)XLb[i1]);
        }
        float p=m0*Ws[l]+m1*Ws[l+32];
#pragma unroll
        for(int o=16;o>=1;o>>=1)p+=__shfl_xor_sync(0xffffffffu,p,o);
        if(l==0) out[OFF_SIGMA+b0+w]=p+bs[0];
    }
    for(int i=tid;i<8192;i+=NTM){
        int ix=axHb(i>>6,i&63);
        out[OFF_OUT+(size_t)b0*512+i]=(float)XHb[ix]+(float)XLb[ix];
    }

    __syncthreads();
    if(wid==0)
        asm volatile("tcgen05.dealloc.cta_group::1.sync.aligned.b32 %0,%1;"::"r"(tb),"r"(256u));

    __syncthreads();
    if(tid==0&&SOK[0]) atomicAdd(&g_ok,1);
#else
    (void)query;(void)latent;(void)b1;(void)bq;(void)bk;(void)bv;(void)bo;(void)fb1;(void)fb2;
    (void)g1;(void)be1;(void)g2;(void)be2;(void)cWq;(void)cbq;(void)cbk;(void)cbv;(void)cWo;
    (void)cbo;(void)Wc;(void)bc;(void)Ws;(void)bs;(void)out;
#endif
}

// =====================================================================
//  FFMA fallback — early-exits when MMA path fully succeeded
// =====================================================================
#define NTF 256
#define F_SX   0
#define F_SCTX 4096
#define F_ST   (4096+16384)
#define F_SW   (F_ST+12288)
#define F_SP   (F_SW+16384)
#define F_SQI  (F_SP+512)
#define F_SCA  (F_SQI+512)
#define F_SMEMF 50688

typedef unsigned long long ull;
__device__ __forceinline__ ull pk2(float lo,float hi){
    ull r; asm("mov.b64 %0,{%1,%2};":"=l"(r):"r"(__float_as_uint(lo)),"r"(__float_as_uint(hi))); return r;
}
__device__ __forceinline__ void fma2(ull &a,ull b,ull c){
    asm("fma.rn.f32x2 %0,%1,%2,%0;":"+l"(a):"l"(b),"l"(c));
}
__device__ __forceinline__ float2 upk(ull v){
    unsigned lo,hi; asm("mov.b64 {%0,%1},%2;":"=r"(lo),"=r"(hi):"l"(v));
    return make_float2(__uint_as_float(lo),__uint_as_float(hi));
}
__device__ __forceinline__ void cp_f4f(float* d,const float* s,int n4,int tid){
    for(int i=tid;i<n4;i+=NTF) reinterpret_cast<float4*>(d)[i]=reinterpret_cast<const float4*>(s)[i];
}
__device__ __forceinline__ void cp_slicef(float* d,const float* s,int tid){
    for(int i=tid;i<1024;i+=NTF){int r=i>>4,c=i&15;
        reinterpret_cast<float4*>(d)[i]=reinterpret_cast<const float4*>(s+r*256)[c];}
}
template<int K,int LDX>
__device__ __forceinline__ void gemm_accF(const float* X,const float* W,ull a01[4],ull a23[4],int c0,int rb){
#pragma unroll 8
    for(int k=0;k<K;++k){
        float4 wv=*reinterpret_cast<const float4*>(W+k*64+c0);
        ull w01=pk2(wv.x,wv.y),w23=pk2(wv.z,wv.w);
#pragma unroll
        for(int r=0;r<4;++r){
            float xv=X[(rb+r)*LDX+k];
            ull xx=pk2(xv,xv);
            fma2(a01[r],w01,xx); fma2(a23[r],w23,xx);
        }
    }
}
template<int K,int LDX,bool RELU>
__device__ __forceinline__ void gemm_blockF(const float* X,const float* W,const float* bias,float* Y,int tid){
    const int c0=(tid&15)*4, rb=(tid>>4)*4;
    ull a01[4]={0,0,0,0},a23[4]={0,0,0,0};
    gemm_accF<K,LDX>(X,W,a01,a23,c0,rb);
    float b0v=bias[c0],b1v=bias[c0+1],b2v=bias[c0+2],b3v=bias[c0+3];
#pragma unroll
    for(int r=0;r<4;++r){
        float2 v01=upk(a01[r]),v23=upk(a23[r]);
        float o0=v01.x+b0v,o1=v01.y+b1v,o2=v23.x+b2v,o3=v23.y+b3v;
        if(RELU){o0=fmaxf(o0,0.f);o1=fmaxf(o1,0.f);o2=fmaxf(o2,0.f);o3=fmaxf(o3,0.f);}
        *reinterpret_cast<float4*>(Y+(rb+r)*64+c0)=make_float4(o0,o1,o2,o3);
    }
}
__device__ __forceinline__ void ln_blockF(const float* Yd,float* Xs,const float* g,const float* be,int w,int l){
    float g0=g[l],g1v=g[l+32],e0=be[l],e1v=be[l+32];
#pragma unroll
    for(int i=0;i<8;++i){
        int r=w*8+i;
        float v0=Yd[r*64+l]+Xs[r*64+l];
        float v1=Yd[r*64+32+l]+Xs[r*64+32+l];
        float s=v0+v1;
#pragma unroll
        for(int o=16;o>=1;o>>=1)s+=__shfl_xor_sync(0xffffffffu,s,o);
        float m=s*(1.f/64.f),d0=v0-m,d1=v1-m,q=d0*d0+d1*d1;
#pragma unroll
        for(int o=16;o>=1;o>>=1)q+=__shfl_xor_sync(0xffffffffu,q,o);
        float inv=rsqrtf(q*(1.f/64.f)+LN_EPS);
        Xs[r*64+l]=d0*inv*g0+e0; Xs[r*64+32+l]=d1*inv*g1v+e1v;
    }
}

extern "C" __global__ void __launch_bounds__(256,1)
radiance_ffma(const float* __restrict__ query,const float* __restrict__ latent,
        const float* __restrict__ W1,const float* __restrict__ b1,
        const float* __restrict__ Wq,const float* __restrict__ bq,
        const float* __restrict__ Wk,const float* __restrict__ bk,
        const float* __restrict__ Wv,const float* __restrict__ bv,
        const float* __restrict__ Wo,const float* __restrict__ bo,
        const float* __restrict__ fW1,const float* __restrict__ fb1,
        const float* __restrict__ fW2,const float* __restrict__ fb2,
        const float* __restrict__ g1,const float* __restrict__ be1,
        const float* __restrict__ g2,const float* __restrict__ be2,
        const float* __restrict__ cWq,const float* __restrict__ cbq,
        const float* __restrict__ cWk,const float* __restrict__ cbk,
        const float* __restrict__ cWv,const float* __restrict__ cbv,
        const float* __restrict__ cWo,const float* __restrict__ cbo,
        const float* __restrict__ Wc,const float* __restrict__ bc,
        const float* __restrict__ Ws,const float* __restrict__ bs,
        float* __restrict__ out){
    if(*(volatile int*)&g_ok==MMA_GRID) return;
    extern __shared__ float smem[];
    float* SX=smem+F_SX; float* SCTX=smem+F_SCTX; float* ST=smem+F_ST;
    float* SW=smem+F_SW; float* SP=smem+F_SP; float* SQI=smem+F_SQI; float* SCA=smem+F_SCA;
    const int tid=threadIdx.x, w=tid>>5, l=tid&31, b0=blockIdx.x*8;
    float* attn_out=out+OFF_ATTN;

    {
        const int c0=(tid&15)*4, rb=(tid>>4)*4;
        ull a01[4]={0,0,0,0},a23[4]={0,0,0,0};
        for(int ch=0;ch<4;++ch){
            __syncthreads();
            cp_f4f(SW,W1+ch*8192,2048,tid);
            for(int i=tid;i<2048;i+=NTF){
                int r=i>>5,j=i&31;
                reinterpret_cast<float4*>(ST)[i]=
                    *reinterpret_cast<const float4*>(latent+(size_t)(b0*8+r)*512+ch*128+j*4);
            }
            __syncthreads();
            gemm_accF<128,128>(ST,SW,a01,a23,c0,rb);
        }
        float b0v=b1[c0],b1v=b1[c0+1],b2v=b1[c0+2],b3v=b1[c0+3];
#pragma unroll
        for(int r=0;r<4;++r){
            float2 v01=upk(a01[r]),v23=upk(a23[r]);
            *reinterpret_cast<float4*>(SX+(rb+r)*64+c0)=
                make_float4(fmaxf(v01.x+b0v,0.f),fmaxf(v01.y+b1v,0.f),
                            fmaxf(v23.x+b2v,0.f),fmaxf(v23.y+b3v,0.f));
        }
    }

    for(int li=0;li<4;++li){
        const float* Wq_i=Wq+li*16384; const float* Wk_i=Wk+li*16384;
        const float* Wv_i=Wv+li*16384;
        for(int h=0;h<4;++h){
            __syncthreads();
            cp_slicef(SW,Wq_i+h*64,tid);
            cp_slicef(SW+4096,Wk_i+h*64,tid);
            cp_slicef(SW+8192,Wv_i+h*64,tid);
            __syncthreads();
            gemm_blockF<64,64,false>(SX,SW,bq+li*256+h*64,ST,tid);
            gemm_blockF<64,64,false>(SX,SW+4096,bk+li*256+h*64,ST+4096,tid);
            gemm_blockF<64,64,false>(SX,SW+8192,bv+li*256+h*64,ST+8192,tid);
            __syncthreads();
            {
                const float* qB=ST+w*512; const float* kB=ST+4096+w*512; const float* vB=ST+8192+w*512;
                int qi=l>>3,kj=l&7;
                float s0=0.f,s1=0.f;
#pragma unroll 8
                for(int d=0;d<64;++d){
                    float kv=kB[kj*64+d];
                    s0+=qB[qi*64+d]*kv; s1+=qB[(qi+4)*64+d]*kv;
                }
                s0*=SC_ATT;s1*=SC_ATT;
                float m0=s0,m1=s1;
#pragma unroll
                for(int o=1;o<8;o<<=1){
                    m0=fmaxf(m0,__shfl_xor_sync(0xffffffffu,m0,o));
                    m1=fmaxf(m1,__shfl_xor_sync(0xffffffffu,m1,o));
                }
                float e0=expf(s0-m0),e1=expf(s1-m1),t0=e0,t1=e1;
#pragma unroll
                for(int o=1;o<8;o<<=1){
                    t0+=__shfl_xor_sync(0xffffffffu,t0,o);
                    t1+=__shfl_xor_sync(0xffffffffu,t1,o);
                }
                float p0=e0/t0,p1=e1/t1;
                SP[w*64+l]=p0; SP[w*64+32+l]=p1;
                size_t ab=(size_t)(b0+w)*1024+li*256+h*64;
                attn_out[ab+l]=p0; attn_out[ab+32+l]=p1;
                __syncwarp();
#pragma unroll
                for(int qq=0;qq<8;++qq){
                    float a0=0.f,a1=0.f;
#pragma unroll
                    for(int kk2=0;kk2<8;++kk2){
                        float p=SP[w*64+qq*8+kk2];
                        a0+=p*vB[kk2*64+l]; a1+=p*vB[kk2*64+32+l];
                    }
                    SCTX[(w*8+qq)*256+h*64+l]=a0;
                    SCTX[(w*8+qq)*256+h*64+32+l]=a1;
                }
            }
        }
        __syncthreads();
        cp_f4f(SW,Wo+li*16384,4096,tid);
        __syncthreads();
        gemm_blockF<256,256,false>(SCTX,SW,bo+li*64,ST,tid);
        __syncthreads();
        ln_blockF(ST,SX,g1+li*64,be1+li*64,w,l);
        __syncthreads();
        cp_f4f(SW,fW1+li*4096,1024,tid);
        cp_f4f(SW+4096,fW2+li*4096,1024,tid);
        __syncthreads();
        gemm_blockF<64,64,true>(SX,SW,fb1+li*64,ST+4096,tid);
        __syncthreads();
        gemm_blockF<64,64,false>(ST+4096,SW+4096,fb2+li*64,ST,tid);
        __syncthreads();
        ln_blockF(ST,SX,g2+li*64,be2+li*64,w,l);
    }

    for(int i=tid;i<512;i+=NTF)
        SQI[i]=query[(size_t)(b0+(i>>6))*64+(i&63)];

    for(int h=0;h<4;++h){
        __syncthreads();
        cp_slicef(SW,cWq+h*64,tid);
        cp_slicef(SW+4096,cWk+h*64,tid);
        cp_slicef(SW+8192,cWv+h*64,tid);
        __syncthreads();
        gemm_blockF<64,64,false>(SX,SW+4096,cbk+h*64,ST,tid);
        gemm_blockF<64,64,false>(SX,SW+8192,cbv+h*64,ST+4096,tid);
        for(int c=l;c<64;c+=32){
            float a=0.f;
#pragma unroll 8
            for(int k2=0;k2<64;++k2) a+=SQI[w*64+k2]*SW[k2*64+c];
            ST[8192+w*64+c]=a+cbq[h*64+c];
        }
        __syncthreads();
        {
            int j=l>>2,part=l&3;
            const float* qrow=ST+8192+w*64; const float* kB=ST+w*512;
            float sc=0.f;
#pragma unroll
            for(int d=part*16;d<part*16+16;++d) sc+=qrow[d]*kB[j*64+d];
            sc+=__shfl_xor_sync(0xffffffffu,sc,1);
            sc+=__shfl_xor_sync(0xffffffffu,sc,2);
            sc*=SC_ATT;
            if(part==0) SP[w*8+j]=sc;
            __syncwarp();
            float mx=-1e30f;
#pragma unroll
            for(int jj=0;jj<8;++jj) mx=fmaxf(mx,SP[w*8+jj]);
            float pe[8],ssum=0.f;
#pragma unroll
            for(int jj=0;jj<8;++jj){pe[jj]=expf(SP[w*8+jj]-mx);ssum+=pe[jj];}
            float inv=1.f/ssum;
            const float* vB=ST+4096+w*512;
            for(int c=l;c<64;c+=32){
                float a=0.f;
#pragma unroll
                for(int jj=0;jj<8;++jj) a+=pe[jj]*vB[jj*64+c];
                SCTX[(w*8)*256+h*64+c]=a*inv;
            }
        }
    }
    __syncthreads();
    cp_f4f(SW,cWo,4096,tid);
    __syncthreads();
    {
        const float* ctx=SCTX+w*2048;
        float a0=0.f,a1=0.f;
#pragma unroll 8
        for(int k2=0;k2<256;++k2){
            float cv=ctx[k2];
            a0+=cv*SW[k2*64+l]; a1+=cv*SW[k2*64+32+l];
        }
        a0=fmaxf(a0+cbo[l],0.f); a1=fmaxf(a1+cbo[l+32],0.f);
        SCA[w*64+l]=a0; SCA[w*64+32+l]=a1;
        __syncwarp();
#pragma unroll
        for(int cq=0;cq<3;++cq){
            float p=SCA[w*64+l]*Wc[l*3+cq]+SCA[w*64+32+l]*Wc[(l+32)*3+cq];
#pragma unroll
            for(int o=16;o>=1;o>>=1)p+=__shfl_xor_sync(0xffffffffu,p,o);
            if(l==0) out[(size_t)(b0+w)*3+cq]=p+bc[cq];
        }
        float m0=-1e30f,m1=-1e30f;
#pragma unroll
        for(int s2=0;s2<8;++s2){
            m0=fmaxf(m0,SX[(w*8+s2)*64+l]);
            m1=fmaxf(m1,SX[(w*8+s2)*64+32+l]);
        }
        float p=m0*Ws[l]+m1*Ws[l+32];
#pragma unroll
        for(int o=16;o>=1;o>>=1)p+=__shfl_xor_sync(0xffffffffu,p,o);
        if(l==0) out[OFF_SIGMA+b0+w]=p+bs[0];
    }
    for(int i=tid;i<4096;i+=NTF)
        out[OFF_OUT+(size_t)b0*512+i]=SX[i];
}

extern "C" void kernel_launch(void* const* d_in,const int* in_sizes,int n_in,
                              void* d_out,int out_size){
    (void)in_sizes;(void)n_in;(void)out_size;
    const float* query=(const float*)d_in[0];
    const float* latent=(const float*)d_in[1];
    const float* W1=(const float*)d_in[2];  const float* b1=(const float*)d_in[3];
    const float* Wq=(const float*)d_in[4];  const float* bq=(const float*)d_in[5];
    const float* Wk=(const float*)d_in[6];  const float* bk=(const float*)d_in[7];
    const float* Wv=(const float*)d_in[8];  const float* bv=(const float*)d_in[9];
    const float* Wo=(const float*)d_in[10]; const float* bo=(const float*)d_in[11];
    const float* fW1=(const float*)d_in[12];const float* fb1=(const float*)d_in[13];
    const float* fW2=(const float*)d_in[14];const float* fb2=(const float*)d_in[15];
    const float* g1=(const float*)d_in[16]; const float* be1=(const float*)d_in[17];
    const float* g2=(const float*)d_in[18]; const float* be2=(const float*)d_in[19];
    const float* cWq=(const float*)d_in[20];const float* cbq=(const float*)d_in[21];
    const float* cWk=(const float*)d_in[22];const float* cbk=(const float*)d_in[23];
    const float* cWv=(const float*)d_in[24];const float* cbv=(const float*)d_in[25];
    const float* cWo=(const float*)d_in[26];const float* cbo=(const float*)d_in[27];
    const float* Wc=(const float*)d_in[28]; const float* bc=(const float*)d_in[29];
    const float* Ws=(const float*)d_in[30]; const float* bs=(const float*)d_in[31];
    float* out=(float*)d_out;

    reset_kernel<<<1,1>>>();
    prep_kernel<<<(88*4096+255)/256,256>>>(W1,Wq,Wk,Wv,Wo,fW1,fW2,cWk,cWv);

    const int smem_mma=27664*sizeof(float);
    cudaFuncSetAttribute(radiance_mma,cudaFuncAttributeMaxDynamicSharedMemorySize,smem_mma);
    radiance_mma<<<MMA_GRID,512,smem_mma>>>(query,latent,b1,bq,bk,bv,bo,fb1,fb2,
        g1,be1,g2,be2,cWq,cbq,cbk,cbv,cWo,cbo,Wc,bc,Ws,bs,out);

    const int smem_ffma=F_SMEMF*sizeof(float);
    cudaFuncSetAttribute(radiance_ffma,cudaFuncAttributeMaxDynamicSharedMemorySize,smem_ffma);
    radiance_ffma<<<BB/8,256,smem_ffma>>>(query,latent,W1,b1,Wq,bq,Wk,bk,Wv,bv,Wo,bo,
        fW1,fb1,fW2,fb2,g1,be1,g2,be2,cWq,cbq,cWk,cbk,cWv,cbv,cWo,cbo,Wc,bc,Ws,bs,out);
}

// round 13
// speedup vs baseline: 1.4333x; 1.4333x over previous
#include <cuda_runtime.h>
#include <cuda_bf16.h>
#include <stdint.h>
#include <math.h>

#if defined(__CUDA_ARCH_FEAT_SM103_ALL) || defined(__CUDA_ARCH_FEAT_SM100_ALL) || defined(__CUDA_ARCH_FEAT_SM101_ALL)
#define HAS_TC 1
#else
#define HAS_TC 0
#endif

#define BB 32768
#define LN_EPS 1e-5f
#define SC_ATT 0.125f
#define OFF_SIGMA (3*BB)
#define OFF_OUT (OFF_SIGMA+BB)
#define OFF_ATTN (OFF_OUT+(size_t)BB*512)
#define MMA_GRID 2048

__device__ __nv_bfloat16 g_Bh[88*8192];   // per tile: 4096 hi then 4096 lo
__device__ int g_ok;

extern "C" __global__ void reset_kernel(){ g_ok = 0; }

__device__ __forceinline__ int axAf(int m,int k){return ((k>>5)<<12)|((m>>3)<<8)|((m&7)<<5)|((k&31)^((m&7)<<2));}
__device__ __forceinline__ int axHb(int r,int k){
    int byte=(r&7)*128+k*2; byte^=((byte>>3)&0x70);
    return ((r>>3)<<9)+(byte>>1);
}
__device__ __forceinline__ void sp2b(float v,__nv_bfloat16&h,__nv_bfloat16&l){
    h=__float2bfloat16(v); l=__float2bfloat16(v-(float)h);
}

extern "C" __global__ void prep_kernel(const float* W1,const float* Wq,const float* Wk,const float* Wv,
        const float* Wo,const float* fW1,const float* fW2,const float* cWk,const float* cWv){
    int idx=blockIdx.x*256+threadIdx.x;
    if(idx>=88*4096)return;
    int tile=idx>>12,j=idx&4095,n=j>>6,k=j&63;
    float v;
    if(tile<8) v=W1[(tile*64+k)*64+n];
    else if(tile<56){int t=tile-8,lh=t/3,wch=t%3,li=lh>>2,h=lh&3;
        const float* W=(wch==0)?Wq:((wch==1)?Wk:Wv);
        v=W[li*16384+k*256+h*64+n];}
    else if(tile<72){int t=tile-56,li=t>>2,h=t&3; v=Wo[li*16384+(h*64+k)*64+n];}
    else if(tile<80){int t=tile-72,li=t>>1; v=((t&1)?fW2:fW1)[li*4096+k*64+n];}
    else if(tile<84) v=cWk[k*256+(tile-80)*64+n];
    else v=cWv[k*256+(tile-84)*64+n];
    __nv_bfloat16 h,l; sp2b(v,h,l);
    int ax=axHb(n,k);
    g_Bh[(size_t)tile*8192+ax]=h;
    g_Bh[(size_t)tile*8192+4096+ax]=l;
}

#if HAS_TC
#define NTM 512
#define IDESC 0x8100490u
#define O_XH 0
#define O_XL 4096
#define O_R0 8192
#define O_R1 12288
#define O_R2 16384
#define O_R3 20480
#define O_SP 24576
#define O_QC 25600
#define O_SQI 26624
#define O_CTL 27648
#define SMEMF 27664

__device__ __forceinline__ uint32_t s2u(const void* p){
    uint32_t a; asm("{.reg .u64 t; cvta.to.shared.u64 t,%1; cvt.u32.u64 %0,t;}":"=r"(a):"l"(p)); return a;
}
__device__ __forceinline__ uint32_t elect1(){
    uint32_t r; asm volatile("{.reg .pred p; elect.sync _|p,0xFFFFFFFF; selp.b32 %0,1,0,p;}":"=r"(r)); return r;
}
__device__ __forceinline__ uint64_t sdesc(uint32_t a){
    const uint64_t b=(uint64_t(2)<<61)|(uint64_t(1)<<46)|(uint64_t(64)<<32)|(uint64_t(1)<<16);
    return b|((a>>4)&0x3FFFu);
}
__device__ __forceinline__ void mma1(uint32_t d,uint64_t ad,uint64_t bd,uint32_t en){
    asm volatile("{.reg .pred p; setp.ne.u32 p,%4,0;\n\t"
        "tcgen05.mma.cta_group::1.kind::f16 [%0],%1,%2,%3,{%5,%5,%5,%5},p;}"
        ::"r"(d),"l"(ad),"l"(bd),"r"(IDESC),"r"(en),"r"(0u):"memory");
}
__device__ __forceinline__ void mma_k64b(uint32_t d,uint32_t a_s,uint32_t b_s,bool acc){
    uint64_t ad=sdesc(a_s),bd=sdesc(b_s);
#pragma unroll
    for(int s=0;s<4;++s)
        mma1(d,ad+(uint32_t)(s*2),bd+(uint32_t)(s*2),(acc||s>0)?1u:0u);
}
__device__ __forceinline__ void mma3b(uint32_t d,uint32_t ah,uint32_t al,uint32_t bh,uint32_t bl,bool acc){
    mma_k64b(d,ah,bh,acc);
    mma_k64b(d,al,bh,true);
    mma_k64b(d,ah,bl,true);
}
#define TCOMMIT(mb) asm volatile("tcgen05.commit.cta_group::1.mbarrier::arrive::one.shared::cluster.b64 [%0];"::"r"(mb):"memory")
#define FPA() asm volatile("fence.proxy.async.shared::cta;":::"memory")
#define TFA() asm volatile("tcgen05.fence::after_thread_sync;":::"memory")
#define TFB() asm volatile("tcgen05.fence::before_thread_sync;":::"memory")

__device__ __forceinline__ bool mb_poll(uint32_t mb,uint32_t par){
    for(int i=0;i<40000;++i){
        uint32_t d;
        asm volatile("{.reg .pred P; mbarrier.try_wait.parity.acquire.cta.shared::cta.b64 P,[%1],%2,0x989680; selp.b32 %0,1,0,P;}"
            :"=r"(d):"r"(mb),"r"(par):"memory");
        if(d) return true;
    }
    return false;
}
__device__ __forceinline__ void ldtm16(uint32_t t,float* f){
    uint32_t r[16];
    asm volatile("tcgen05.ld.sync.aligned.32x32b.x16.b32 {%0,%1,%2,%3,%4,%5,%6,%7,%8,%9,%10,%11,%12,%13,%14,%15},[%16];"
        :"=r"(r[0]),"=r"(r[1]),"=r"(r[2]),"=r"(r[3]),"=r"(r[4]),"=r"(r[5]),"=r"(r[6]),"=r"(r[7]),
         "=r"(r[8]),"=r"(r[9]),"=r"(r[10]),"=r"(r[11]),"=r"(r[12]),"=r"(r[13]),"=r"(r[14]),"=r"(r[15])
        :"r"(t));
    asm volatile("tcgen05.wait::ld.sync.aligned;":::"memory");
#pragma unroll
    for(int i=0;i<16;++i) f[i]=__uint_as_float(r[i]);
}
__device__ __forceinline__ void epi_fullf(uint32_t t,const float* bias,float* X,int m_r,int c0){
    float r[16]; ldtm16(t,r);
#pragma unroll
    for(int i=0;i<16;i+=4){
        float4 v=make_float4(r[i]+bias[i],r[i+1]+bias[i+1],r[i+2]+bias[i+2],r[i+3]+bias[i+3]);
        *reinterpret_cast<float4*>(X+axAf(m_r,c0+i))=v;
    }
}
__device__ __forceinline__ void epi_splitb(uint32_t t,const float* bias,
        __nv_bfloat16* Hb,__nv_bfloat16* Lb,int m_r,int c0,bool relu){
    float r[16]; ldtm16(t,r);
#pragma unroll
    for(int j=0;j<8;++j){
        float v0=r[2*j]+bias[2*j], v1=r[2*j+1]+bias[2*j+1];
        if(relu){v0=fmaxf(v0,0.f);v1=fmaxf(v1,0.f);}
        __nv_bfloat16 h0,l0,h1,l1;
        sp2b(v0,h0,l0); sp2b(v1,h1,l1);
        int k=c0+2*j;
        int byte=(m_r&7)*128+k*2; byte^=((byte>>3)&0x70);
        int base=((m_r>>3)<<10)+byte;
        __nv_bfloat162 hp; hp.x=h0; hp.y=h1;
        __nv_bfloat162 lp; lp.x=l0; lp.y=l1;
        *reinterpret_cast<__nv_bfloat162*>(reinterpret_cast<char*>(Hb)+base)=hp;
        *reinterpret_cast<__nv_bfloat162*>(reinterpret_cast<char*>(Lb)+base)=lp;
    }
}
__device__ __forceinline__ void cp_f4m(float* d,const float* s,int n4,int tid){
    for(int i=tid;i<n4;i+=NTM) reinterpret_cast<float4*>(d)[i]=reinterpret_cast<const float4*>(s)[i];
}
__device__ __forceinline__ void cp_pair(float* dst,int tile,int tid){
    const float4* s=reinterpret_cast<const float4*>(g_Bh+(size_t)tile*8192);
    for(int i=tid;i<1024;i+=NTM) reinterpret_cast<float4*>(dst)[i]=s[i];
}
__device__ __forceinline__ void cp_slicem(float* d,const float* s,int tid){
    for(int i=tid;i<1024;i+=NTM){int r=i>>4,c=i&15;
        reinterpret_cast<float4*>(d)[i]=reinterpret_cast<const float4*>(s+r*256)[c];}
}
__device__ __forceinline__ void ln_b(const float* Y,__nv_bfloat16* XHb,__nv_bfloat16* XLb,
        const float* g,const float* be,int w,int l){
    float g0=g[l],g1v=g[l+32],e0=be[l],e1v=be[l+32];
#pragma unroll
    for(int i=0;i<8;++i){
        int r=w*8+i;
        int y0=axAf(r,l), y1=axAf(r,l+32);
        int b0i=axHb(r,l), b1i=axHb(r,l+32);
        float v0=Y[y0]+(float)XHb[b0i]+(float)XLb[b0i];
        float v1=Y[y1]+(float)XHb[b1i]+(float)XLb[b1i];
        float s=v0+v1;
#pragma unroll
        for(int o=16;o>=1;o>>=1)s+=__shfl_xor_sync(0xffffffffu,s,o);
        float m=s*(1.f/64.f),d0=v0-m,d1=v1-m,q=d0*d0+d1*d1;
#pragma unroll
        for(int o=16;o>=1;o>>=1)q+=__shfl_xor_sync(0xffffffffu,q,o);
        float inv=rsqrtf(q*(1.f/64.f)+LN_EPS);
        float a=d0*inv*g0+e0, b=d1*inv*g1v+e1v;
        sp2b(a,XHb[b0i],XLb[b0i]);
        sp2b(b,XHb[b1i],XLb[b1i]);
    }
}
#define WAITX do{ \
    if(tid==0){ if(SOK[0] && !mb_poll(mbv[wc&1],(uint32_t)((wc>>1)&1))) SOK[0]=0; } \
    __syncthreads(); \
    wc++; }while(0)
#endif

extern "C" __global__ void __launch_bounds__(512,2)
#if HAS_TC
__cluster_dims__(1,1,1)
#endif
radiance_mma(const float* __restrict__ query,const float* __restrict__ latent,
        const float* __restrict__ b1,const float* __restrict__ bq,const float* __restrict__ bk,
        const float* __restrict__ bv,const float* __restrict__ bo,const float* __restrict__ fb1,
        const float* __restrict__ fb2,const float* __restrict__ g1,const float* __restrict__ be1,
        const float* __restrict__ g2,const float* __restrict__ be2,const float* __restrict__ cWq,
        const float* __restrict__ cbq,const float* __restrict__ cbk,const float* __restrict__ cbv,
        const float* __restrict__ cWo,const float* __restrict__ cbo,const float* __restrict__ Wc,
        const float* __restrict__ bc,const float* __restrict__ Ws,const float* __restrict__ bs,
        float* __restrict__ out){
#if HAS_TC
    extern __shared__ float smem[];
    float* R0f=smem+O_R0; float* R1f=smem+O_R1; float* R2f=smem+O_R2; float* R3f=smem+O_R3;
    __nv_bfloat16* XHb=reinterpret_cast<__nv_bfloat16*>(smem+O_XH);
    __nv_bfloat16* XLb=reinterpret_cast<__nv_bfloat16*>(smem+O_XL);
    float* SP=smem+O_SP; float* QC=smem+O_QC; float* SQI=smem+O_SQI;
    volatile int* SOK=reinterpret_cast<volatile int*>(smem+O_CTL+6);
    const int tid=threadIdx.x,wid=tid>>5,l=tid&31,w=wid;
    const int b0=blockIdx.x*16;
    const int m_r=(wid&3)*32+l, c0=(wid>>2)*16;
    uint32_t sb=s2u(smem), ctl=sb+O_CTL*4;
    uint32_t mbv[2]={ctl+8,ctl+16};
    int cc=0, wc=0; (void)cc;

    if(tid==0){
        asm volatile("mbarrier.init.shared.b64 [%0],1;"::"r"(mbv[0]):"memory");
        asm volatile("mbarrier.init.shared.b64 [%0],1;"::"r"(mbv[1]):"memory");
        SOK[0]=1;
    }
    if(wid==0){
        asm volatile("tcgen05.alloc.cta_group::1.sync.aligned.shared::cta.b32 [%0],%1;"::"r"(ctl),"r"(256u):"memory");
        asm volatile("tcgen05.relinquish_alloc_permit.cta_group::1.sync.aligned;");
    }
    FPA(); __syncthreads();
    uint32_t tb; asm("ld.shared.b32 %0,[%1];":"=r"(tb):"r"(ctl));
    const uint32_t DQ=tb,DK=tb+64,DV=tb+128,DO=tb+192;
    const uint32_t aXH=sb+O_XH*4,aXL=sb+O_XL*4;
    const uint32_t aR0=sb+O_R0*4,aR1=sb+O_R1*4,aR2=sb+O_R2*4,aR3=sb+O_R3*4;
    float* attn_out=out+OFF_ATTN;

    // ======== stage0: X = relu(latent@W1+b1), K=512 in 8 chunks ========
    for(int ch=0;ch<8;++ch){
        if(ch>=2) WAITX;
        __nv_bfloat16* Ah=reinterpret_cast<__nv_bfloat16*>((ch&1)?R2f:R0f);
        __nv_bfloat16* Al=reinterpret_cast<__nv_bfloat16*>((ch&1)?R3f:R1f);
        float* Bp=(ch&1)?(smem+O_XL):(smem+O_XH);
        uint32_t aAh=(ch&1)?aR2:aR0, aAl=(ch&1)?aR3:aR1;
        uint32_t aBp=(ch&1)?aXL:aXH;
        for(int i=tid;i<2048;i+=NTM){
            int m=i>>4,k4=(i&15)<<2;
            float4 v=*reinterpret_cast<const float4*>(latent+(size_t)(b0*8+m)*512+ch*64+k4);
            __nv_bfloat16 h0,l0,h1,l1,h2,l2,h3,l3;
            sp2b(v.x,h0,l0); sp2b(v.y,h1,l1); sp2b(v.z,h2,l2); sp2b(v.w,h3,l3);
            int byte=(m&7)*128+k4*2; byte^=((byte>>3)&0x70);
            int base=((m>>3)<<10)+byte;
            __nv_bfloat162 p01h; p01h.x=h0; p01h.y=h1;
            __nv_bfloat162 p23h; p23h.x=h2; p23h.y=h3;
            __nv_bfloat162 p01l; p01l.x=l0; p01l.y=l1;
            __nv_bfloat162 p23l; p23l.x=l2; p23l.y=l3;
            *reinterpret_cast<__nv_bfloat162*>(reinterpret_cast<char*>(Ah)+base)=p01h;
            *reinterpret_cast<__nv_bfloat162*>(reinterpret_cast<char*>(Ah)+base+4)=p23h;
            *reinterpret_cast<__nv_bfloat162*>(reinterpret_cast<char*>(Al)+base)=p01l;
            *reinterpret_cast<__nv_bfloat162*>(reinterpret_cast<char*>(Al)+base+4)=p23l;
        }
        cp_pair(Bp,ch,tid);
        FPA(); __syncthreads();
        if(wid==0){ TFA();
            if(elect1()){
                mma3b(DQ,aAh,aAl,aBp,aBp+8192,ch>0);
                TCOMMIT(mbv[cc&1]);
            }
        }
        cc++;
    }
    WAITX; WAITX;
    TFA();
    epi_splitb(DQ+c0,b1+c0,XHb,XLb,m_r,c0,true);
    TFB(); FPA(); __syncthreads();

    // ======== 4 transformer layers ========
    for(int li=0;li<4;++li){
        for(int h=0;h<4;++h){
            if(h>0) WAITX;                 // O-mma(h-1)
            int base=8+(li*4+h)*3;
            cp_pair(R0f,base,tid);         // Bq pair
            if(h==0) cp_pair(R1f,base+1,tid);   // Bk pair (h>0 pre-staged)
            cp_pair(R2f,base+2,tid);       // Bv pair
            FPA(); __syncthreads();
            if(wid==0){ TFA();
                if(elect1()){
                    mma3b(DQ,aXH,aXL,aR0,aR0+8192,false);
                    mma3b(DK,aXH,aXL,aR1,aR1+8192,false);
                    mma3b(DV,aXH,aXL,aR2,aR2+8192,false);
                    TCOMMIT(mbv[cc&1]);
                }
            }
            cc++;
            WAITX;
            TFA();
            epi_fullf(DQ+c0,bq+li*256+h*64+c0,R0f,m_r,c0);   // Q fp32 -> R0R1
            epi_fullf(DK+c0,bk+li*256+h*64+c0,R2f,m_r,c0);   // K fp32 -> R2R3
            TFB();
            __syncthreads();
            {   // scores per warp (= batch), fp32
                const int qi=l>>3,kj=l&7;
                float s0=0.f,s1=0.f;
#pragma unroll
                for(int d4=0;d4<64;d4+=4){
                    float4 kv=*reinterpret_cast<const float4*>(R2f+axAf(w*8+kj,d4));
                    float4 q0=*reinterpret_cast<const float4*>(R0f+axAf(w*8+qi,d4));
                    float4 q1=*reinterpret_cast<const float4*>(R0f+axAf(w*8+qi+4,d4));
                    s0+=q0.x*kv.x+q0.y*kv.y+q0.z*kv.z+q0.w*kv.w;
                    s1+=q1.x*kv.x+q1.y*kv.y+q1.z*kv.z+q1.w*kv.w;
                }
                s0*=SC_ATT;s1*=SC_ATT;
                float m0=s0,m1=s1;
#pragma unroll
                for(int o=1;o<8;o<<=1){
                    m0=fmaxf(m0,__shfl_xor_sync(0xffffffffu,m0,o));
                    m1=fmaxf(m1,__shfl_xor_sync(0xffffffffu,m1,o));
                }
                float e0=__expf(s0-m0),e1=__expf(s1-m1),t0=e0,t1=e1;
#pragma unroll
                for(int o=1;o<8;o<<=1){
                    t0+=__shfl_xor_sync(0xffffffffu,t0,o);
                    t1+=__shfl_xor_sync(0xffffffffu,t1,o);
                }
                float p0=e0/t0,p1=e1/t1;
                SP[w*64+l]=p0; SP[w*64+32+l]=p1;
                size_t ab=(size_t)(b0+w)*1024+li*256+h*64;
                attn_out[ab+l]=p0; attn_out[ab+32+l]=p1;
            }
            __syncthreads();               // all warps done with Q (R0R1)
            TFA();
            epi_fullf(DV+c0,bv+li*256+h*64+c0,R0f,m_r,c0);   // V fp32 -> R0R1
            TFB();
            __syncthreads();
            {   // ctx = P@V ; split bf16 pair into R2(hi)/R3(lo) (K dead)
                float a0[8],a1[8];
#pragma unroll
                for(int q2=0;q2<8;++q2){a0[q2]=0.f;a1[q2]=0.f;}
#pragma unroll
                for(int kk=0;kk<8;++kk){
                    float v0=R0f[axAf(w*8+kk,l)],v1=R0f[axAf(w*8+kk,l+32)];
#pragma unroll
                    for(int q2=0;q2<8;++q2){
                        float p=SP[w*64+q2*8+kk];
                        a0[q2]+=p*v0; a1[q2]+=p*v1;
                    }
                }
                __nv_bfloat16* CH=reinterpret_cast<__nv_bfloat16*>(R2f);
                __nv_bfloat16* CL=reinterpret_cast<__nv_bfloat16*>(R3f);
#pragma unroll
                for(int q2=0;q2<8;++q2){
                    int i0=axHb(w*8+q2,l), i1=axHb(w*8+q2,l+32);
                    sp2b(a0[q2],CH[i0],CL[i0]);
                    sp2b(a1[q2],CH[i1],CL[i1]);
                }
            }
            FPA(); __syncthreads();        // ctx visible; V dead
            cp_pair(R0f,56+li*4+h,tid);    // Wo pair
            FPA(); __syncthreads();
            if(wid==0){ TFA();
                if(elect1()){ mma3b(DO,aR2,aR3,aR0,aR0+8192,h>0); TCOMMIT(mbv[cc&1]); }
            }
            cc++;
            // pre-stage next head's Bk into R1 while O-mma is in flight
            if(h<3) cp_pair(R1f,8+(li*4+h+1)*3+1,tid);
        } // heads
        WAITX;
        TFA();
        epi_fullf(DO+c0,bo+li*64+c0,R0f,m_r,c0);    // Y fp32 -> R0R1
        TFB(); __syncthreads();
        ln_b(R0f,XHb,XLb,g1+li*64,be1+li*64,w,l);
        cp_pair(R2f,72+li*2,tid);                   // fW1 pair
        cp_pair(R3f,73+li*2,tid);                   // fW2 pair
        FPA(); __syncthreads();
        if(wid==0){ TFA();
            if(elect1()){ mma3b(DQ,aXH,aXL,aR2,aR2+8192,false); TCOMMIT(mbv[cc&1]); }
        }
        cc++;
        WAITX;
        TFA();
        epi_splitb(DQ+c0,fb1+li*64+c0,
                   reinterpret_cast<__nv_bfloat16*>(R0f),
                   reinterpret_cast<__nv_bfloat16*>(R1f),m_r,c0,true);  // h1 pair
        TFB(); FPA(); __syncthreads();
        if(wid==0){ TFA();
            if(elect1()){ mma3b(DK,aR0,aR1,aR3,aR3+8192,false); TCOMMIT(mbv[cc&1]); }
        }
        cc++;
        WAITX;
        TFA();
        epi_fullf(DK+c0,fb2+li*64+c0,R2f,m_r,c0);   // Y2 fp32 -> R2R3
        TFB(); __syncthreads();
        ln_b(R2f,XHb,XLb,g2+li*64,be2+li*64,w,l);
        FPA(); __syncthreads();
    } // layers

    // ======== cross attention ========
    for(int i=tid;i<1024;i+=NTM) SQI[i]=query[(size_t)(b0+(i>>6))*64+(i&63)];
    float ca0=0.f,ca1=0.f;
    for(int h=0;h<4;++h){
        cp_pair(R0f,80+h,tid);
        cp_pair(R1f,84+h,tid);
        cp_slicem(R2f,cWq+h*64,tid);
        cp_f4m(R3f,cWo+h*4096,1024,tid);
        FPA(); __syncthreads();
        if(wid==0){ TFA();
            if(elect1()){
                mma3b(DQ,aXH,aXL,aR0,aR0+8192,false);   // Kc
                mma3b(DK,aXH,aXL,aR1,aR1+8192,false);   // Vc
                TCOMMIT(mbv[cc&1]);
            }
        }
        cc++;
        for(int c=l;c<64;c+=32){
            float a=0.f;
#pragma unroll 8
            for(int k2=0;k2<64;++k2) a+=SQI[w*64+k2]*R2f[k2*64+c];
            QC[w*64+c]=a+cbq[h*64+c];
        }
        __syncwarp();
        WAITX;
        TFA();
        epi_fullf(DQ+c0,cbk+h*64+c0,R0f,m_r,c0);    // Kc fp32 -> R0R1
        TFB();
        __syncthreads();
        {
            const int j=l>>2,part=l&3;
            float sc=0.f;
#pragma unroll
            for(int d4=part*16;d4<part*16+16;d4+=4){
                float4 kv=*reinterpret_cast<const float4*>(R0f+axAf(w*8+j,d4));
                sc+=QC[w*64+d4]*kv.x+QC[w*64+d4+1]*kv.y+QC[w*64+d4+2]*kv.z+QC[w*64+d4+3]*kv.w;
            }
            sc+=__shfl_xor_sync(0xffffffffu,sc,1);
            sc+=__shfl_xor_sync(0xffffffffu,sc,2);
            sc*=SC_ATT;
            if(part==0) SP[w*64+j]=sc;
        }
        __syncthreads();
        TFA();
        epi_fullf(DK+c0,cbv+h*64+c0,R0f,m_r,c0);    // Vc fp32 -> R0R1
        TFB();
        __syncthreads();
        {
            float mx=-1e30f;
#pragma unroll
            for(int jj=0;jj<8;++jj) mx=fmaxf(mx,SP[w*64+jj]);
            float pe[8],ss=0.f;
#pragma unroll
            for(int jj=0;jj<8;++jj){pe[jj]=__expf(SP[w*64+jj]-mx);ss+=pe[jj];}
            float inv=1.f/ss;
            for(int c=l;c<64;c+=32){
                float a=0.f;
#pragma unroll
                for(int jj=0;jj<8;++jj) a+=pe[jj]*R0f[axAf(w*8+jj,c)];
                QC[w*64+c]=a*inv;
            }
            __syncwarp();
#pragma unroll 8
            for(int k2=0;k2<64;++k2){
                float cv=QC[w*64+k2];
                ca0+=cv*R3f[k2*64+l];
                ca1+=cv*R3f[k2*64+32+l];
            }
        }
        __syncthreads();
    }
    // ======== heads: color, sigma, out ========
    {
        float a0=fmaxf(ca0+cbo[l],0.f),a1=fmaxf(ca1+cbo[l+32],0.f);
#pragma unroll
        for(int cq=0;cq<3;++cq){
            float p=a0*Wc[l*3+cq]+a1*Wc[(l+32)*3+cq];
#pragma unroll
            for(int o=16;o>=1;o>>=1)p+=__shfl_xor_sync(0xffffffffu,p,o);
            if(l==0) out[(size_t)(b0+w)*3+cq]=p+bc[cq];
        }
        float m0=-1e30f,m1=-1e30f;
#pragma unroll
        for(int s2=0;s2<8;++s2){
            int i0=axHb(w*8+s2,l), i1=axHb(w*8+s2,l+32);
            m0=fmaxf(m0,(float)XHb[i0]+(float)XLb[i0]);
            m1=fmaxf(m1,(float)XHb[i1]+(float)XLb[i1]);
        }
        float p=m0*Ws[l]+m1*Ws[l+32];
#pragma unroll
        for(int o=16;o>=1;o>>=1)p+=__shfl_xor_sync(0xffffffffu,p,o);
        if(l==0) out[OFF_SIGMA+b0+w]=p+bs[0];
    }
    for(int i=tid;i<8192;i+=NTM){
        int ix=axHb(i>>6,i&63);
        out[OFF_OUT+(size_t)b0*512+i]=(float)XHb[ix]+(float)XLb[ix];
    }

    __syncthreads();
    if(wid==0)
        asm volatile("tcgen05.dealloc.cta_group::1.sync.aligned.b32 %0,%1;"::"r"(tb),"r"(256u));

    __syncthreads();
    if(tid==0&&SOK[0]) atomicAdd(&g_ok,1);
#else
    (void)query;(void)latent;(void)b1;(void)bq;(void)bk;(void)bv;(void)bo;(void)fb1;(void)fb2;
    (void)g1;(void)be1;(void)g2;(void)be2;(void)cWq;(void)cbq;(void)cbk;(void)cbv;(void)cWo;
    (void)cbo;(void)Wc;(void)bc;(void)Ws;(void)bs;(void)out;
#endif
}

// =====================================================================
//  FFMA fallback — early-exits when MMA path fully succeeded
// =====================================================================
#define NTF 256
#define F_SX   0
#define F_SCTX 4096
#define F_ST   (4096+16384)
#define F_SW   (F_ST+12288)
#define F_SP   (F_SW+16384)
#define F_SQI  (F_SP+512)
#define F_SCA  (F_SQI+512)
#define F_SMEMF 50688

typedef unsigned long long ull;
__device__ __forceinline__ ull pk2(float lo,float hi){
    ull r; asm("mov.b64 %0,{%1,%2};":"=l"(r):"r"(__float_as_uint(lo)),"r"(__float_as_uint(hi))); return r;
}
__device__ __forceinline__ void fma2(ull &a,ull b,ull c){
    asm("fma.rn.f32x2 %0,%1,%2,%0;":"+l"(a):"l"(b),"l"(c));
}
__device__ __forceinline__ float2 upk(ull v){
    unsigned lo,hi; asm("mov.b64 {%0,%1},%2;":"=r"(lo),"=r"(hi):"l"(v));
    return make_float2(__uint_as_float(lo),__uint_as_float(hi));
}
__device__ __forceinline__ void cp_f4f(float* d,const float* s,int n4,int tid){
    for(int i=tid;i<n4;i+=NTF) reinterpret_cast<float4*>(d)[i]=reinterpret_cast<const float4*>(s)[i];
}
__device__ __forceinline__ void cp_slicef(float* d,const float* s,int tid){
    for(int i=tid;i<1024;i+=NTF){int r=i>>4,c=i&15;
        reinterpret_cast<float4*>(d)[i]=reinterpret_cast<const float4*>(s+r*256)[c];}
}
template<int K,int LDX>
__device__ __forceinline__ void gemm_accF(const float* X,const float* W,ull a01[4],ull a23[4],int c0,int rb){
#pragma unroll 8
    for(int k=0;k<K;++k){
        float4 wv=*reinterpret_cast<const float4*>(W+k*64+c0);
        ull w01=pk2(wv.x,wv.y),w23=pk2(wv.z,wv.w);
#pragma unroll
        for(int r=0;r<4;++r){
            float xv=X[(rb+r)*LDX+k];
            ull xx=pk2(xv,xv);
            fma2(a01[r],w01,xx); fma2(a23[r],w23,xx);
        }
    }
}
template<int K,int LDX,bool RELU>
__device__ __forceinline__ void gemm_blockF(const float* X,const float* W,const float* bias,float* Y,int tid){
    const int c0=(tid&15)*4, rb=(tid>>4)*4;
    ull a01[4]={0,0,0,0},a23[4]={0,0,0,0};
    gemm_accF<K,LDX>(X,W,a01,a23,c0,rb);
    float b0v=bias[c0],b1v=bias[c0+1],b2v=bias[c0+2],b3v=bias[c0+3];
#pragma unroll
    for(int r=0;r<4;++r){
        float2 v01=upk(a01[r]),v23=upk(a23[r]);
        float o0=v01.x+b0v,o1=v01.y+b1v,o2=v23.x+b2v,o3=v23.y+b3v;
        if(RELU){o0=fmaxf(o0,0.f);o1=fmaxf(o1,0.f);o2=fmaxf(o2,0.f);o3=fmaxf(o3,0.f);}
        *reinterpret_cast<float4*>(Y+(rb+r)*64+c0)=make_float4(o0,o1,o2,o3);
    }
}
__device__ __forceinline__ void ln_blockF(const float* Yd,float* Xs,const float* g,const float* be,int w,int l){
    float g0=g[l],g1v=g[l+32],e0=be[l],e1v=be[l+32];
#pragma unroll
    for(int i=0;i<8;++i){
        int r=w*8+i;
        float v0=Yd[r*64+l]+Xs[r*64+l];
        float v1=Yd[r*64+32+l]+Xs[r*64+32+l];
        float s=v0+v1;
#pragma unroll
        for(int o=16;o>=1;o>>=1)s+=__shfl_xor_sync(0xffffffffu,s,o);
        float m=s*(1.f/64.f),d0=v0-m,d1=v1-m,q=d0*d0+d1*d1;
#pragma unroll
        for(int o=16;o>=1;o>>=1)q+=__shfl_xor_sync(0xffffffffu,q,o);
        float inv=rsqrtf(q*(1.f/64.f)+LN_EPS);
        Xs[r*64+l]=d0*inv*g0+e0; Xs[r*64+32+l]=d1*inv*g1v+e1v;
    }
}

extern "C" __global__ void __launch_bounds__(256,1)
radiance_ffma(const float* __restrict__ query,const float* __restrict__ latent,
        const float* __restrict__ W1,const float* __restrict__ b1,
        const float* __restrict__ Wq,const float* __restrict__ bq,
        const float* __restrict__ Wk,const float* __restrict__ bk,
        const float* __restrict__ Wv,const float* __restrict__ bv,
        const float* __restrict__ Wo,const float* __restrict__ bo,
        const float* __restrict__ fW1,const float* __restrict__ fb1,
        const float* __restrict__ fW2,const float* __restrict__ fb2,
        const float* __restrict__ g1,const float* __restrict__ be1,
        const float* __restrict__ g2,const float* __restrict__ be2,
        const float* __restrict__ cWq,const float* __restrict__ cbq,
        const float* __restrict__ cWk,const float* __restrict__ cbk,
        const float* __restrict__ cWv,const float* __restrict__ cbv,
        const float* __restrict__ cWo,const float* __restrict__ cbo,
        const float* __restrict__ Wc,const float* __restrict__ bc,
        const float* __restrict__ Ws,const float* __restrict__ bs,
        float* __restrict__ out){
    if(*(volatile int*)&g_ok==MMA_GRID) return;
    extern __shared__ float smem[];
    float* SX=smem+F_SX; float* SCTX=smem+F_SCTX; float* ST=smem+F_ST;
    float* SW=smem+F_SW; float* SP=smem+F_SP; float* SQI=smem+F_SQI; float* SCA=smem+F_SCA;
    const int tid=threadIdx.x, w=tid>>5, l=tid&31, b0=blockIdx.x*8;
    float* attn_out=out+OFF_ATTN;

    {
        const int c0=(tid&15)*4, rb=(tid>>4)*4;
        ull a01[4]={0,0,0,0},a23[4]={0,0,0,0};
        for(int ch=0;ch<4;++ch){
            __syncthreads();
            cp_f4f(SW,W1+ch*8192,2048,tid);
            for(int i=tid;i<2048;i+=NTF){
                int r=i>>5,j=i&31;
                reinterpret_cast<float4*>(ST)[i]=
                    *reinterpret_cast<const float4*>(latent+(size_t)(b0*8+r)*512+ch*128+j*4);
            }
            __syncthreads();
            gemm_accF<128,128>(ST,SW,a01,a23,c0,rb);
        }
        float b0v=b1[c0],b1v=b1[c0+1],b2v=b1[c0+2],b3v=b1[c0+3];
#pragma unroll
        for(int r=0;r<4;++r){
            float2 v01=upk(a01[r]),v23=upk(a23[r]);
            *reinterpret_cast<float4*>(SX+(rb+r)*64+c0)=
                make_float4(fmaxf(v01.x+b0v,0.f),fmaxf(v01.y+b1v,0.f),
                            fmaxf(v23.x+b2v,0.f),fmaxf(v23.y+b3v,0.f));
        }
    }

    for(int li=0;li<4;++li){
        const float* Wq_i=Wq+li*16384; const float* Wk_i=Wk+li*16384;
        const float* Wv_i=Wv+li*16384;
        for(int h=0;h<4;++h){
            __syncthreads();
            cp_slicef(SW,Wq_i+h*64,tid);
            cp_slicef(SW+4096,Wk_i+h*64,tid);
            cp_slicef(SW+8192,Wv_i+h*64,tid);
            __syncthreads();
            gemm_blockF<64,64,false>(SX,SW,bq+li*256+h*64,ST,tid);
            gemm_blockF<64,64,false>(SX,SW+4096,bk+li*256+h*64,ST+4096,tid);
            gemm_blockF<64,64,false>(SX,SW+8192,bv+li*256+h*64,ST+8192,tid);
            __syncthreads();
            {
                const float* qB=ST+w*512; const float* kB=ST+4096+w*512; const float* vB=ST+8192+w*512;
                int qi=l>>3,kj=l&7;
                float s0=0.f,s1=0.f;
#pragma unroll 8
                for(int d=0;d<64;++d){
                    float kv=kB[kj*64+d];
                    s0+=qB[qi*64+d]*kv; s1+=qB[(qi+4)*64+d]*kv;
                }
                s0*=SC_ATT;s1*=SC_ATT;
                float m0=s0,m1=s1;
#pragma unroll
                for(int o=1;o<8;o<<=1){
                    m0=fmaxf(m0,__shfl_xor_sync(0xffffffffu,m0,o));
                    m1=fmaxf(m1,__shfl_xor_sync(0xffffffffu,m1,o));
                }
                float e0=expf(s0-m0),e1=expf(s1-m1),t0=e0,t1=e1;
#pragma unroll
                for(int o=1;o<8;o<<=1){
                    t0+=__shfl_xor_sync(0xffffffffu,t0,o);
                    t1+=__shfl_xor_sync(0xffffffffu,t1,o);
                }
                float p0=e0/t0,p1=e1/t1;
                SP[w*64+l]=p0; SP[w*64+32+l]=p1;
                size_t ab=(size_t)(b0+w)*1024+li*256+h*64;
                attn_out[ab+l]=p0; attn_out[ab+32+l]=p1;
                __syncwarp();
#pragma unroll
                for(int qq=0;qq<8;++qq){
                    float a0=0.f,a1=0.f;
#pragma unroll
                    for(int kk2=0;kk2<8;++kk2){
                        float p=SP[w*64+qq*8+kk2];
                        a0+=p*vB[kk2*64+l]; a1+=p*vB[kk2*64+32+l];
                    }
                    SCTX[(w*8+qq)*256+h*64+l]=a0;
                    SCTX[(w*8+qq)*256+h*64+32+l]=a1;
                }
            }
        }
        __syncthreads();
        cp_f4f(SW,Wo+li*16384,4096,tid);
        __syncthreads();
        gemm_blockF<256,256,false>(SCTX,SW,bo+li*64,ST,tid);
        __syncthreads();
        ln_blockF(ST,SX,g1+li*64,be1+li*64,w,l);
        __syncthreads();
        cp_f4f(SW,fW1+li*4096,1024,tid);
        cp_f4f(SW+4096,fW2+li*4096,1024,tid);
        __syncthreads();
        gemm_blockF<64,64,true>(SX,SW,fb1+li*64,ST+4096,tid);
        __syncthreads();
        gemm_blockF<64,64,false>(ST+4096,SW+4096,fb2+li*64,ST,tid);
        __syncthreads();
        ln_blockF(ST,SX,g2+li*64,be2+li*64,w,l);
    }

    for(int i=tid;i<512;i+=NTF)
        SQI[i]=query[(size_t)(b0+(i>>6))*64+(i&63)];

    for(int h=0;h<4;++h){
        __syncthreads();
        cp_slicef(SW,cWq+h*64,tid);
        cp_slicef(SW+4096,cWk+h*64,tid);
        cp_slicef(SW+8192,cWv+h*64,tid);
        __syncthreads();
        gemm_blockF<64,64,false>(SX,SW+4096,cbk+h*64,ST,tid);
        gemm_blockF<64,64,false>(SX,SW+8192,cbv+h*64,ST+4096,tid);
        for(int c=l;c<64;c+=32){
            float a=0.f;
#pragma unroll 8
            for(int k2=0;k2<64;++k2) a+=SQI[w*64+k2]*SW[k2*64+c];
            ST[8192+w*64+c]=a+cbq[h*64+c];
        }
        __syncthreads();
        {
            int j=l>>2,part=l&3;
            const float* qrow=ST+8192+w*64; const float* kB=ST+w*512;
            float sc=0.f;
#pragma unroll
            for(int d=part*16;d<part*16+16;++d) sc+=qrow[d]*kB[j*64+d];
            sc+=__shfl_xor_sync(0xffffffffu,sc,1);
            sc+=__shfl_xor_sync(0xffffffffu,sc,2);
            sc*=SC_ATT;
            if(part==0) SP[w*8+j]=sc;
            __syncwarp();
            float mx=-1e30f;
#pragma unroll
            for(int jj=0;jj<8;++jj) mx=fmaxf(mx,SP[w*8+jj]);
            float pe[8],ssum=0.f;
#pragma unroll
            for(int jj=0;jj<8;++jj){pe[jj]=expf(SP[w*8+jj]-mx);ssum+=pe[jj];}
            float inv=1.f/ssum;
            const float* vB=ST+4096+w*512;
            for(int c=l;c<64;c+=32){
                float a=0.f;
#pragma unroll
                for(int jj=0;jj<8;++jj) a+=pe[jj]*vB[jj*64+c];
                SCTX[(w*8)*256+h*64+c]=a*inv;
            }
        }
    }
    __syncthreads();
    cp_f4f(SW,cWo,4096,tid);
    __syncthreads();
    {
        const float* ctx=SCTX+w*2048;
        float a0=0.f,a1=0.f;
#pragma unroll 8
        for(int k2=0;k2<256;++k2){
            float cv=ctx[k2];
            a0+=cv*SW[k2*64+l]; a1+=cv*SW[k2*64+32+l];
        }
        a0=fmaxf(a0+cbo[l],0.f); a1=fmaxf(a1+cbo[l+32],0.f);
        SCA[w*64+l]=a0; SCA[w*64+32+l]=a1;
        __syncwarp();
#pragma unroll
        for(int cq=0;cq<3;++cq){
            float p=SCA[w*64+l]*Wc[l*3+cq]+SCA[w*64+32+l]*Wc[(l+32)*3+cq];
#pragma unroll
            for(int o=16;o>=1;o>>=1)p+=__shfl_xor_sync(0xffffffffu,p,o);
            if(l==0) out[(size_t)(b0+w)*3+cq]=p+bc[cq];
        }
        float m0=-1e30f,m1=-1e30f;
#pragma unroll
        for(int s2=0;s2<8;++s2){
            m0=fmaxf(m0,SX[(w*8+s2)*64+l]);
            m1=fmaxf(m1,SX[(w*8+s2)*64+32+l]);
        }
        float p=m0*Ws[l]+m1*Ws[l+32];
#pragma unroll
        for(int o=16;o>=1;o>>=1)p+=__shfl_xor_sync(0xffffffffu,p,o);
        if(l==0) out[OFF_SIGMA+b0+w]=p+bs[0];
    }
    for(int i=tid;i<4096;i+=NTF)
        out[OFF_OUT+(size_t)b0*512+i]=SX[i];
}

extern "C" void kernel_launch(void* const* d_in,const int* in_sizes,int n_in,
                              void* d_out,int out_size){
    (void)in_sizes;(void)n_in;(void)out_size;
    const float* query=(const float*)d_in[0];
    const float* latent=(const float*)d_in[1];
    const float* W1=(const float*)d_in[2];  const float* b1=(const float*)d_in[3];
    const float* Wq=(const float*)d_in[4];  const float* bq=(const float*)d_in[5];
    const float* Wk=(const float*)d_in[6];  const float* bk=(const float*)d_in[7];
    const float* Wv=(const float*)d_in[8];  const float* bv=(const float*)d_in[9];
    const float* Wo=(const float*)d_in[10]; const float* bo=(const float*)d_in[11];
    const float* fW1=(const float*)d_in[12];const float* fb1=(const float*)d_in[13];
    const float* fW2=(const float*)d_in[14];const float* fb2=(const float*)d_in[15];
    const float* g1=(const float*)d_in[16]; const float* be1=(const float*)d_in[17];
    const float* g2=(const float*)d_in[18]; const float* be2=(const float*)d_in[19];
    const float* cWq=(const float*)d_in[20];const float* cbq=(const float*)d_in[21];
    const float* cWk=(const float*)d_in[22];const float* cbk=(const float*)d_in[23];
    const float* cWv=(const float*)d_in[24];const float* cbv=(const float*)d_in[25];
    const float* cWo=(const float*)d_in[26];const float* cbo=(const float*)d_in[27];
    const float* Wc=(const float*)d_in[28]; const float* bc=(const float*)d_in[29];
    const float* Ws=(const float*)d_in[30]; const float* bs=(const float*)d_in[31];
    float* out=(float*)d_out;

    reset_kernel<<<1,1>>>();
    prep_kernel<<<(88*4096+255)/256,256>>>(W1,Wq,Wk,Wv,Wo,fW1,fW2,cWk,cWv);

    const int smem_mma=27664*sizeof(float);
    cudaFuncSetAttribute(radiance_mma,cudaFuncAttributeMaxDynamicSharedMemorySize,smem_mma);
    radiance_mma<<<MMA_GRID,512,smem_mma>>>(query,latent,b1,bq,bk,bv,bo,fb1,fb2,
        g1,be1,g2,be2,cWq,cbq,cbk,cbv,cWo,cbo,Wc,bc,Ws,bs,out);

    const int smem_ffma=F_SMEMF*sizeof(float);
    cudaFuncSetAttribute(radiance_ffma,cudaFuncAttributeMaxDynamicSharedMemorySize,smem_ffma);
    radiance_ffma<<<BB/8,256,smem_ffma>>>(query,latent,W1,b1,Wq,bq,Wk,bk,Wv,bv,Wo,bo,
        fW1,fb1,fW2,fb2,g1,be1,g2,be2,cWq,cbq,cWk,cbk,cWv,cbv,cWo,cbo,Wc,bc,Ws,bs,out);
}

// round 14
// speedup vs baseline: 1.4907x; 1.0400x over previous
#include <cuda_runtime.h>
#include <cuda_bf16.h>
#include <stdint.h>
#include <math.h>

#if defined(__CUDA_ARCH_FEAT_SM103_ALL) || defined(__CUDA_ARCH_FEAT_SM100_ALL) || defined(__CUDA_ARCH_FEAT_SM101_ALL)
#define HAS_TC 1
#else
#define HAS_TC 0
#endif

#define BB 32768
#define LN_EPS 1e-5f
#define SC_ATT 0.125f
#define OFF_SIGMA (3*BB)
#define OFF_OUT (OFF_SIGMA+BB)
#define OFF_ATTN (OFF_OUT+(size_t)BB*512)
#define MMA_GRID 2048

__device__ __nv_bfloat16 g_Bh[88*8192];   // per tile: 4096 hi then 4096 lo
__device__ int g_ok;

extern "C" __global__ void reset_kernel(){ g_ok = 0; }

__device__ __forceinline__ int axAf(int m,int k){return ((k>>5)<<12)|((m>>3)<<8)|((m&7)<<5)|((k&31)^((m&7)<<2));}
__device__ __forceinline__ int axHb(int r,int k){
    int byte=(r&7)*128+k*2; byte^=((byte>>3)&0x70);
    return ((r>>3)<<9)+(byte>>1);
}
__device__ __forceinline__ void sp2b(float v,__nv_bfloat16&h,__nv_bfloat16&l){
    h=__float2bfloat16(v); l=__float2bfloat16(v-(float)h);
}

extern "C" __global__ void prep_kernel(const float* W1,const float* Wq,const float* Wk,const float* Wv,
        const float* Wo,const float* fW1,const float* fW2,const float* cWk,const float* cWv){
    int idx=blockIdx.x*256+threadIdx.x;
    if(idx>=88*4096)return;
    int tile=idx>>12,j=idx&4095,n=j>>6,k=j&63;
    float v;
    if(tile<8) v=W1[(tile*64+k)*64+n];
    else if(tile<56){int t=tile-8,lh=t/3,wch=t%3,li=lh>>2,h=lh&3;
        const float* W=(wch==0)?Wq:((wch==1)?Wk:Wv);
        v=W[li*16384+k*256+h*64+n];}
    else if(tile<72){int t=tile-56,li=t>>2,h=t&3; v=Wo[li*16384+(h*64+k)*64+n];}
    else if(tile<80){int t=tile-72,li=t>>1; v=((t&1)?fW2:fW1)[li*4096+k*64+n];}
    else if(tile<84) v=cWk[k*256+(tile-80)*64+n];
    else v=cWv[k*256+(tile-84)*64+n];
    __nv_bfloat16 h,l; sp2b(v,h,l);
    int ax=axHb(n,k);
    g_Bh[(size_t)tile*8192+ax]=h;
    g_Bh[(size_t)tile*8192+4096+ax]=l;
}

#if HAS_TC
#define NTM 512
#define IDESC 0x8100490u
#define O_XH 0
#define O_XL 4096
#define O_R0 8192
#define O_R1 12288
#define O_R2 16384
#define O_R3 20480
#define O_SP 24576
#define O_QC 25600
#define O_SQI 26624
#define O_CTL 27648
#define SMEMF 27664

__device__ __forceinline__ uint32_t s2u(const void* p){
    uint32_t a; asm("{.reg .u64 t; cvta.to.shared.u64 t,%1; cvt.u32.u64 %0,t;}":"=r"(a):"l"(p)); return a;
}
__device__ __forceinline__ uint32_t elect1(){
    uint32_t r; asm volatile("{.reg .pred p; elect.sync _|p,0xFFFFFFFF; selp.b32 %0,1,0,p;}":"=r"(r)); return r;
}
__device__ __forceinline__ uint64_t sdesc(uint32_t a){
    const uint64_t b=(uint64_t(2)<<61)|(uint64_t(1)<<46)|(uint64_t(64)<<32)|(uint64_t(1)<<16);
    return b|((a>>4)&0x3FFFu);
}
__device__ __forceinline__ void mma1(uint32_t d,uint64_t ad,uint64_t bd,uint32_t en){
    asm volatile("{.reg .pred p; setp.ne.u32 p,%4,0;\n\t"
        "tcgen05.mma.cta_group::1.kind::f16 [%0],%1,%2,%3,{%5,%5,%5,%5},p;}"
        ::"r"(d),"l"(ad),"l"(bd),"r"(IDESC),"r"(en),"r"(0u):"memory");
}
__device__ __forceinline__ void mma_k64b(uint32_t d,uint32_t a_s,uint32_t b_s,bool acc){
    uint64_t ad=sdesc(a_s),bd=sdesc(b_s);
#pragma unroll
    for(int s=0;s<4;++s)
        mma1(d,ad+(uint32_t)(s*2),bd+(uint32_t)(s*2),(acc||s>0)?1u:0u);
}
__device__ __forceinline__ void mma3b(uint32_t d,uint32_t ah,uint32_t al,uint32_t bh,uint32_t bl,bool acc){
    mma_k64b(d,ah,bh,acc);
    mma_k64b(d,al,bh,true);
    mma_k64b(d,ah,bl,true);
}
#define TCOMMIT(mb) asm volatile("tcgen05.commit.cta_group::1.mbarrier::arrive::one.shared::cluster.b64 [%0];"::"r"(mb):"memory")
#define FPA() asm volatile("fence.proxy.async.shared::cta;":::"memory")
#define TFA() asm volatile("tcgen05.fence::after_thread_sync;":::"memory")
#define TFB() asm volatile("tcgen05.fence::before_thread_sync;":::"memory")

// sleeping bounded wait: HW TRYWAIT with suspend hint (no hot spin)
__device__ __forceinline__ bool mb_poll(uint32_t mb,uint32_t par){
    for(int i=0;i<40000;++i){
        uint32_t d;
        asm volatile("{.reg .pred P; mbarrier.try_wait.parity.acquire.cta.shared::cta.b64 P,[%1],%2,0x989680; selp.b32 %0,1,0,P;}"
            :"=r"(d):"r"(mb),"r"(par):"memory");
        if(d) return true;
    }
    return false;
}
__device__ __forceinline__ void ldtm16(uint32_t t,float* f){
    uint32_t r[16];
    asm volatile("tcgen05.ld.sync.aligned.32x32b.x16.b32 {%0,%1,%2,%3,%4,%5,%6,%7,%8,%9,%10,%11,%12,%13,%14,%15},[%16];"
        :"=r"(r[0]),"=r"(r[1]),"=r"(r[2]),"=r"(r[3]),"=r"(r[4]),"=r"(r[5]),"=r"(r[6]),"=r"(r[7]),
         "=r"(r[8]),"=r"(r[9]),"=r"(r[10]),"=r"(r[11]),"=r"(r[12]),"=r"(r[13]),"=r"(r[14]),"=r"(r[15])
        :"r"(t));
    asm volatile("tcgen05.wait::ld.sync.aligned;":::"memory");
#pragma unroll
    for(int i=0;i<16;++i) f[i]=__uint_as_float(r[i]);
}
__device__ __forceinline__ void epi_fullf(uint32_t t,const float* bias,float* X,int m_r,int c0){
    float r[16]; ldtm16(t,r);
#pragma unroll
    for(int i=0;i<16;i+=4){
        float4 v=make_float4(r[i]+bias[i],r[i+1]+bias[i+1],r[i+2]+bias[i+2],r[i+3]+bias[i+3]);
        *reinterpret_cast<float4*>(X+axAf(m_r,c0+i))=v;
    }
}
__device__ __forceinline__ void epi_splitb(uint32_t t,const float* bias,
        __nv_bfloat16* Hb,__nv_bfloat16* Lb,int m_r,int c0,bool relu){
    float r[16]; ldtm16(t,r);
#pragma unroll
    for(int j=0;j<8;++j){
        float v0=r[2*j]+bias[2*j], v1=r[2*j+1]+bias[2*j+1];
        if(relu){v0=fmaxf(v0,0.f);v1=fmaxf(v1,0.f);}
        __nv_bfloat16 h0,l0,h1,l1;
        sp2b(v0,h0,l0); sp2b(v1,h1,l1);
        int k=c0+2*j;
        int byte=(m_r&7)*128+k*2; byte^=((byte>>3)&0x70);
        int base=((m_r>>3)<<10)+byte;
        __nv_bfloat162 hp; hp.x=h0; hp.y=h1;
        __nv_bfloat162 lp; lp.x=l0; lp.y=l1;
        *reinterpret_cast<__nv_bfloat162*>(reinterpret_cast<char*>(Hb)+base)=hp;
        *reinterpret_cast<__nv_bfloat162*>(reinterpret_cast<char*>(Lb)+base)=lp;
    }
}
__device__ __forceinline__ void cp_f4m(float* d,const float* s,int n4,int tid){
    for(int i=tid;i<n4;i+=NTM) reinterpret_cast<float4*>(d)[i]=reinterpret_cast<const float4*>(s)[i];
}
__device__ __forceinline__ void cp_pair(float* dst,int tile,int tid){
    const float4* s=reinterpret_cast<const float4*>(g_Bh+(size_t)tile*8192);
    for(int i=tid;i<1024;i+=NTM) reinterpret_cast<float4*>(dst)[i]=s[i];
}
__device__ __forceinline__ void cp_slicem(float* d,const float* s,int tid){
    for(int i=tid;i<1024;i+=NTM){int r=i>>4,c=i&15;
        reinterpret_cast<float4*>(d)[i]=reinterpret_cast<const float4*>(s+r*256)[c];}
}
__device__ __forceinline__ void ln_b(const float* Y,__nv_bfloat16* XHb,__nv_bfloat16* XLb,
        const float* g,const float* be,int w,int l){
    float g0=g[l],g1v=g[l+32],e0=be[l],e1v=be[l+32];
#pragma unroll
    for(int i=0;i<8;++i){
        int r=w*8+i;
        int y0=axAf(r,l), y1=axAf(r,l+32);
        int b0i=axHb(r,l), b1i=axHb(r,l+32);
        float v0=Y[y0]+(float)XHb[b0i]+(float)XLb[b0i];
        float v1=Y[y1]+(float)XHb[b1i]+(float)XLb[b1i];
        float s=v0+v1;
#pragma unroll
        for(int o=16;o>=1;o>>=1)s+=__shfl_xor_sync(0xffffffffu,s,o);
        float m=s*(1.f/64.f),d0=v0-m,d1=v1-m,q=d0*d0+d1*d1;
#pragma unroll
        for(int o=16;o>=1;o>>=1)q+=__shfl_xor_sync(0xffffffffu,q,o);
        float inv=rsqrtf(q*(1.f/64.f)+LN_EPS);
        float a=d0*inv*g0+e0, b=d1*inv*g1v+e1v;
        sp2b(a,XHb[b0i],XLb[b0i]);
        sp2b(b,XHb[b1i],XLb[b1i]);
    }
}
#define WAITX do{ \
    if(tid==0){ if(SOK[0] && !mb_poll(mbv[wc&1],(uint32_t)((wc>>1)&1))) SOK[0]=0; } \
    __syncthreads(); \
    wc++; }while(0)
#endif

extern "C" __global__ void __launch_bounds__(512,2)
#if HAS_TC
__cluster_dims__(1,1,1)
#endif
radiance_mma(const float* __restrict__ query,const float* __restrict__ latent,
        const float* __restrict__ b1,const float* __restrict__ bq,const float* __restrict__ bk,
        const float* __restrict__ bv,const float* __restrict__ bo,const float* __restrict__ fb1,
        const float* __restrict__ fb2,const float* __restrict__ g1,const float* __restrict__ be1,
        const float* __restrict__ g2,const float* __restrict__ be2,const float* __restrict__ cWq,
        const float* __restrict__ cbq,const float* __restrict__ cbk,const float* __restrict__ cbv,
        const float* __restrict__ cWo,const float* __restrict__ cbo,const float* __restrict__ Wc,
        const float* __restrict__ bc,const float* __restrict__ Ws,const float* __restrict__ bs,
        float* __restrict__ out){
#if HAS_TC
    extern __shared__ float smem[];
    float* R0f=smem+O_R0; float* R1f=smem+O_R1; float* R2f=smem+O_R2; float* R3f=smem+O_R3;
    __nv_bfloat16* XHb=reinterpret_cast<__nv_bfloat16*>(smem+O_XH);
    __nv_bfloat16* XLb=reinterpret_cast<__nv_bfloat16*>(smem+O_XL);
    float* SP=smem+O_SP; float* QC=smem+O_QC; float* SQI=smem+O_SQI;
    volatile int* SOK=reinterpret_cast<volatile int*>(smem+O_CTL+6);
    const int tid=threadIdx.x,wid=tid>>5,l=tid&31,w=wid;
    const int b0=blockIdx.x*16;
    const int m_r=(wid&3)*32+l, c0=(wid>>2)*16;
    uint32_t sb=s2u(smem), ctl=sb+O_CTL*4;
    uint32_t mbv[2]={ctl+8,ctl+16};
    int cc=0, wc=0; (void)cc;

    if(tid==0){
        asm volatile("mbarrier.init.shared.b64 [%0],1;"::"r"(mbv[0]):"memory");
        asm volatile("mbarrier.init.shared.b64 [%0],1;"::"r"(mbv[1]):"memory");
        SOK[0]=1;
    }
    if(wid==0){
        asm volatile("tcgen05.alloc.cta_group::1.sync.aligned.shared::cta.b32 [%0],%1;"::"r"(ctl),"r"(256u):"memory");
        asm volatile("tcgen05.relinquish_alloc_permit.cta_group::1.sync.aligned;");
    }
    FPA(); __syncthreads();
    uint32_t tb; asm("ld.shared.b32 %0,[%1];":"=r"(tb):"r"(ctl));
    const uint32_t DQ=tb,DK=tb+64,DV=tb+128,DO=tb+192;
    const uint32_t aXH=sb+O_XH*4,aXL=sb+O_XL*4;
    const uint32_t aR0=sb+O_R0*4,aR1=sb+O_R1*4,aR2=sb+O_R2*4,aR3=sb+O_R3*4;
    float* attn_out=out+OFF_ATTN;

    // ======== stage0: X = relu(latent@W1+b1), K=512 in 8 chunks ========
    for(int ch=0;ch<8;++ch){
        if(ch>=2) WAITX;
        __nv_bfloat16* Ah=reinterpret_cast<__nv_bfloat16*>((ch&1)?R2f:R0f);
        __nv_bfloat16* Al=reinterpret_cast<__nv_bfloat16*>((ch&1)?R3f:R1f);
        float* Bp=(ch&1)?(smem+O_XL):(smem+O_XH);
        uint32_t aAh=(ch&1)?aR2:aR0, aAl=(ch&1)?aR3:aR1;
        uint32_t aBp=(ch&1)?aXL:aXH;
        for(int i=tid;i<2048;i+=NTM){
            int m=i>>4,k4=(i&15)<<2;
            float4 v=*reinterpret_cast<const float4*>(latent+(size_t)(b0*8+m)*512+ch*64+k4);
            __nv_bfloat16 h0,l0,h1,l1,h2,l2,h3,l3;
            sp2b(v.x,h0,l0); sp2b(v.y,h1,l1); sp2b(v.z,h2,l2); sp2b(v.w,h3,l3);
            int byte=(m&7)*128+k4*2; byte^=((byte>>3)&0x70);
            int base=((m>>3)<<10)+byte;
            __nv_bfloat162 p01h; p01h.x=h0; p01h.y=h1;
            __nv_bfloat162 p23h; p23h.x=h2; p23h.y=h3;
            __nv_bfloat162 p01l; p01l.x=l0; p01l.y=l1;
            __nv_bfloat162 p23l; p23l.x=l2; p23l.y=l3;
            *reinterpret_cast<__nv_bfloat162*>(reinterpret_cast<char*>(Ah)+base)=p01h;
            *reinterpret_cast<__nv_bfloat162*>(reinterpret_cast<char*>(Ah)+base+4)=p23h;
            *reinterpret_cast<__nv_bfloat162*>(reinterpret_cast<char*>(Al)+base)=p01l;
            *reinterpret_cast<__nv_bfloat162*>(reinterpret_cast<char*>(Al)+base+4)=p23l;
        }
        cp_pair(Bp,ch,tid);
        FPA(); __syncthreads();
        if(wid==0){ TFA();
            if(elect1()){
                mma3b(DQ,aAh,aAl,aBp,aBp+8192,ch>0);
                TCOMMIT(mbv[cc&1]);
            }
        }
        cc++;
    }
    WAITX; WAITX;
    TFA();
    epi_splitb(DQ+c0,b1+c0,XHb,XLb,m_r,c0,true);
    TFB(); FPA(); __syncthreads();

    // ======== 4 transformer layers ========
    for(int li=0;li<4;++li){
        for(int h=0;h<4;++h){
            if(h>0) WAITX;                 // O-mma(h-1)
            int base=8+(li*4+h)*3;
            cp_pair(R0f,base,tid);         // Bq pair
            cp_pair(R1f,base+1,tid);       // Bk pair
            cp_pair(R2f,base+2,tid);       // Bv pair
            FPA(); __syncthreads();
            if(wid==0){ TFA();
                if(elect1()){
                    mma3b(DQ,aXH,aXL,aR0,aR0+8192,false);
                    mma3b(DK,aXH,aXL,aR1,aR1+8192,false);
                    mma3b(DV,aXH,aXL,aR2,aR2+8192,false);
                    TCOMMIT(mbv[cc&1]);
                }
            }
            cc++;
            WAITX;
            TFA();
            epi_fullf(DQ+c0,bq+li*256+h*64+c0,R0f,m_r,c0);   // Q fp32 -> R0R1
            epi_fullf(DK+c0,bk+li*256+h*64+c0,R2f,m_r,c0);   // K fp32 -> R2R3
            TFB();
            __syncthreads();
            {   // scores per warp (= batch), fp32
                const int qi=l>>3,kj=l&7;
                float s0=0.f,s1=0.f;
#pragma unroll
                for(int d4=0;d4<64;d4+=4){
                    float4 kv=*reinterpret_cast<const float4*>(R2f+axAf(w*8+kj,d4));
                    float4 q0=*reinterpret_cast<const float4*>(R0f+axAf(w*8+qi,d4));
                    float4 q1=*reinterpret_cast<const float4*>(R0f+axAf(w*8+qi+4,d4));
                    s0+=q0.x*kv.x+q0.y*kv.y+q0.z*kv.z+q0.w*kv.w;
                    s1+=q1.x*kv.x+q1.y*kv.y+q1.z*kv.z+q1.w*kv.w;
                }
                s0*=SC_ATT;s1*=SC_ATT;
                float m0=s0,m1=s1;
#pragma unroll
                for(int o=1;o<8;o<<=1){
                    m0=fmaxf(m0,__shfl_xor_sync(0xffffffffu,m0,o));
                    m1=fmaxf(m1,__shfl_xor_sync(0xffffffffu,m1,o));
                }
                float e0=__expf(s0-m0),e1=__expf(s1-m1),t0=e0,t1=e1;
#pragma unroll
                for(int o=1;o<8;o<<=1){
                    t0+=__shfl_xor_sync(0xffffffffu,t0,o);
                    t1+=__shfl_xor_sync(0xffffffffu,t1,o);
                }
                float p0=e0/t0,p1=e1/t1;
                SP[w*64+l]=p0; SP[w*64+32+l]=p1;
                size_t ab=(size_t)(b0+w)*1024+li*256+h*64;
                attn_out[ab+l]=p0; attn_out[ab+32+l]=p1;
            }
            __syncthreads();               // all warps done with Q (R0R1)
            TFA();
            epi_fullf(DV+c0,bv+li*256+h*64+c0,R0f,m_r,c0);   // V fp32 -> R0R1
            TFB();
            __syncthreads();
            {   // ctx = P@V ; split bf16 pair into R2(hi)/R3(lo) (K dead)
                float a0[8],a1[8];
#pragma unroll
                for(int q2=0;q2<8;++q2){a0[q2]=0.f;a1[q2]=0.f;}
#pragma unroll
                for(int kk=0;kk<8;++kk){
                    float v0=R0f[axAf(w*8+kk,l)],v1=R0f[axAf(w*8+kk,l+32)];
#pragma unroll
                    for(int q2=0;q2<8;++q2){
                        float p=SP[w*64+q2*8+kk];
                        a0[q2]+=p*v0; a1[q2]+=p*v1;
                    }
                }
                __nv_bfloat16* CH=reinterpret_cast<__nv_bfloat16*>(R2f);
                __nv_bfloat16* CL=reinterpret_cast<__nv_bfloat16*>(R3f);
#pragma unroll
                for(int q2=0;q2<8;++q2){
                    int i0=axHb(w*8+q2,l), i1=axHb(w*8+q2,l+32);
                    sp2b(a0[q2],CH[i0],CL[i0]);
                    sp2b(a1[q2],CH[i1],CL[i1]);
                }
            }
            FPA(); __syncthreads();        // ctx visible; V dead
            cp_pair(R0f,56+li*4+h,tid);    // Wo pair
            FPA(); __syncthreads();
            if(wid==0){ TFA();
                if(elect1()){ mma3b(DO,aR2,aR3,aR0,aR0+8192,h>0); TCOMMIT(mbv[cc&1]); }
            }
            cc++;
        } // heads
        WAITX;
        TFA();
        epi_fullf(DO+c0,bo+li*64+c0,R0f,m_r,c0);    // Y fp32 -> R0R1
        TFB(); __syncthreads();
        ln_b(R0f,XHb,XLb,g1+li*64,be1+li*64,w,l);
        cp_pair(R2f,72+li*2,tid);                   // fW1 pair
        cp_pair(R3f,73+li*2,tid);                   // fW2 pair
        FPA(); __syncthreads();
        if(wid==0){ TFA();
            if(elect1()){ mma3b(DQ,aXH,aXL,aR2,aR2+8192,false); TCOMMIT(mbv[cc&1]); }
        }
        cc++;
        WAITX;
        TFA();
        epi_splitb(DQ+c0,fb1+li*64+c0,
                   reinterpret_cast<__nv_bfloat16*>(R0f),
                   reinterpret_cast<__nv_bfloat16*>(R1f),m_r,c0,true);  // h1 pair
        TFB(); FPA(); __syncthreads();
        if(wid==0){ TFA();
            if(elect1()){ mma3b(DK,aR0,aR1,aR3,aR3+8192,false); TCOMMIT(mbv[cc&1]); }
        }
        cc++;
        WAITX;
        TFA();
        epi_fullf(DK+c0,fb2+li*64+c0,R2f,m_r,c0);   // Y2 fp32 -> R2R3
        TFB(); __syncthreads();
        ln_b(R2f,XHb,XLb,g2+li*64,be2+li*64,w,l);
        FPA(); __syncthreads();
    } // layers

    // ======== cross attention ========
    for(int i=tid;i<1024;i+=NTM) SQI[i]=query[(size_t)(b0+(i>>6))*64+(i&63)];
    float ca0=0.f,ca1=0.f;
    for(int h=0;h<4;++h){
        cp_pair(R0f,80+h,tid);
        cp_pair(R1f,84+h,tid);
        cp_slicem(R2f,cWq+h*64,tid);
        cp_f4m(R3f,cWo+h*4096,1024,tid);
        FPA(); __syncthreads();
        if(wid==0){ TFA();
            if(elect1()){
                mma3b(DQ,aXH,aXL,aR0,aR0+8192,false);   // Kc
                mma3b(DK,aXH,aXL,aR1,aR1+8192,false);   // Vc
                TCOMMIT(mbv[cc&1]);
            }
        }
        cc++;
        for(int c=l;c<64;c+=32){
            float a=0.f;
#pragma unroll 8
            for(int k2=0;k2<64;++k2) a+=SQI[w*64+k2]*R2f[k2*64+c];
            QC[w*64+c]=a+cbq[h*64+c];
        }
        __syncwarp();
        WAITX;
        TFA();
        epi_fullf(DQ+c0,cbk+h*64+c0,R0f,m_r,c0);    // Kc fp32 -> R0R1
        TFB();
        __syncthreads();
        {
            const int j=l>>2,part=l&3;
            float sc=0.f;
#pragma unroll
            for(int d4=part*16;d4<part*16+16;d4+=4){
                float4 kv=*reinterpret_cast<const float4*>(R0f+axAf(w*8+j,d4));
                sc+=QC[w*64+d4]*kv.x+QC[w*64+d4+1]*kv.y+QC[w*64+d4+2]*kv.z+QC[w*64+d4+3]*kv.w;
            }
            sc+=__shfl_xor_sync(0xffffffffu,sc,1);
            sc+=__shfl_xor_sync(0xffffffffu,sc,2);
            sc*=SC_ATT;
            if(part==0) SP[w*64+j]=sc;
        }
        __syncthreads();
        TFA();
        epi_fullf(DK+c0,cbv+h*64+c0,R0f,m_r,c0);    // Vc fp32 -> R0R1
        TFB();
        __syncthreads();
        {
            float mx=-1e30f;
#pragma unroll
            for(int jj=0;jj<8;++jj) mx=fmaxf(mx,SP[w*64+jj]);
            float pe[8],ss=0.f;
#pragma unroll
            for(int jj=0;jj<8;++jj){pe[jj]=__expf(SP[w*64+jj]-mx);ss+=pe[jj];}
            float inv=1.f/ss;
            for(int c=l;c<64;c+=32){
                float a=0.f;
#pragma unroll
                for(int jj=0;jj<8;++jj) a+=pe[jj]*R0f[axAf(w*8+jj,c)];
                QC[w*64+c]=a*inv;
            }
            __syncwarp();
#pragma unroll 8
            for(int k2=0;k2<64;++k2){
                float cv=QC[w*64+k2];
                ca0+=cv*R3f[k2*64+l];
                ca1+=cv*R3f[k2*64+32+l];
            }
        }
        __syncthreads();
    }
    // ======== heads: color, sigma, out ========
    {
        float a0=fmaxf(ca0+cbo[l],0.f),a1=fmaxf(ca1+cbo[l+32],0.f);
#pragma unroll
        for(int cq=0;cq<3;++cq){
            float p=a0*Wc[l*3+cq]+a1*Wc[(l+32)*3+cq];
#pragma unroll
            for(int o=16;o>=1;o>>=1)p+=__shfl_xor_sync(0xffffffffu,p,o);
            if(l==0) out[(size_t)(b0+w)*3+cq]=p+bc[cq];
        }
        float m0=-1e30f,m1=-1e30f;
#pragma unroll
        for(int s2=0;s2<8;++s2){
            int i0=axHb(w*8+s2,l), i1=axHb(w*8+s2,l+32);
            m0=fmaxf(m0,(float)XHb[i0]+(float)XLb[i0]);
            m1=fmaxf(m1,(float)XHb[i1]+(float)XLb[i1]);
        }
        float p=m0*Ws[l]+m1*Ws[l+32];
#pragma unroll
        for(int o=16;o>=1;o>>=1)p+=__shfl_xor_sync(0xffffffffu,p,o);
        if(l==0) out[OFF_SIGMA+b0+w]=p+bs[0];
    }
    for(int i=tid;i<8192;i+=NTM){
        int ix=axHb(i>>6,i&63);
        out[OFF_OUT+(size_t)b0*512+i]=(float)XHb[ix]+(float)XLb[ix];
    }

    __syncthreads();
    if(wid==0)
        asm volatile("tcgen05.dealloc.cta_group::1.sync.aligned.b32 %0,%1;"::"r"(tb),"r"(256u));

    __syncthreads();
    if(tid==0&&SOK[0]) atomicAdd(&g_ok,1);
#else
    (void)query;(void)latent;(void)b1;(void)bq;(void)bk;(void)bv;(void)bo;(void)fb1;(void)fb2;
    (void)g1;(void)be1;(void)g2;(void)be2;(void)cWq;(void)cbq;(void)cbk;(void)cbv;(void)cWo;
    (void)cbo;(void)Wc;(void)bc;(void)Ws;(void)bs;(void)out;
#endif
}

// =====================================================================
//  FFMA fallback — early-exits when MMA path fully succeeded
// =====================================================================
#define NTF 256
#define F_SX   0
#define F_SCTX 4096
#define F_ST   (4096+16384)
#define F_SW   (F_ST+12288)
#define F_SP   (F_SW+16384)
#define F_SQI  (F_SP+512)
#define F_SCA  (F_SQI+512)
#define F_SMEMF 50688

typedef unsigned long long ull;
__device__ __forceinline__ ull pk2(float lo,float hi){
    ull r; asm("mov.b64 %0,{%1,%2};":"=l"(r):"r"(__float_as_uint(lo)),"r"(__float_as_uint(hi))); return r;
}
__device__ __forceinline__ void fma2(ull &a,ull b,ull c){
    asm("fma.rn.f32x2 %0,%1,%2,%0;":"+l"(a):"l"(b),"l"(c));
}
__device__ __forceinline__ float2 upk(ull v){
    unsigned lo,hi; asm("mov.b64 {%0,%1},%2;":"=r"(lo),"=r"(hi):"l"(v));
    return make_float2(__uint_as_float(lo),__uint_as_float(hi));
}
__device__ __forceinline__ void cp_f4f(float* d,const float* s,int n4,int tid){
    for(int i=tid;i<n4;i+=NTF) reinterpret_cast<float4*>(d)[i]=reinterpret_cast<const float4*>(s)[i];
}
__device__ __forceinline__ void cp_slicef(float* d,const float* s,int tid){
    for(int i=tid;i<1024;i+=NTF){int r=i>>4,c=i&15;
        reinterpret_cast<float4*>(d)[i]=reinterpret_cast<const float4*>(s+r*256)[c];}
}
template<int K,int LDX>
__device__ __forceinline__ void gemm_accF(const float* X,const float* W,ull a01[4],ull a23[4],int c0,int rb){
#pragma unroll 8
    for(int k=0;k<K;++k){
        float4 wv=*reinterpret_cast<const float4*>(W+k*64+c0);
        ull w01=pk2(wv.x,wv.y),w23=pk2(wv.z,wv.w);
#pragma unroll
        for(int r=0;r<4;++r){
            float xv=X[(rb+r)*LDX+k];
            ull xx=pk2(xv,xv);
            fma2(a01[r],w01,xx); fma2(a23[r],w23,xx);
        }
    }
}
template<int K,int LDX,bool RELU>
__device__ __forceinline__ void gemm_blockF(const float* X,const float* W,const float* bias,float* Y,int tid){
    const int c0=(tid&15)*4, rb=(tid>>4)*4;
    ull a01[4]={0,0,0,0},a23[4]={0,0,0,0};
    gemm_accF<K,LDX>(X,W,a01,a23,c0,rb);
    float b0v=bias[c0],b1v=bias[c0+1],b2v=bias[c0+2],b3v=bias[c0+3];
#pragma unroll
    for(int r=0;r<4;++r){
        float2 v01=upk(a01[r]),v23=upk(a23[r]);
        float o0=v01.x+b0v,o1=v01.y+b1v,o2=v23.x+b2v,o3=v23.y+b3v;
        if(RELU){o0=fmaxf(o0,0.f);o1=fmaxf(o1,0.f);o2=fmaxf(o2,0.f);o3=fmaxf(o3,0.f);}
        *reinterpret_cast<float4*>(Y+(rb+r)*64+c0)=make_float4(o0,o1,o2,o3);
    }
}
__device__ __forceinline__ void ln_blockF(const float* Yd,float* Xs,const float* g,const float* be,int w,int l){
    float g0=g[l],g1v=g[l+32],e0=be[l],e1v=be[l+32];
#pragma unroll
    for(int i=0;i<8;++i){
        int r=w*8+i;
        float v0=Yd[r*64+l]+Xs[r*64+l];
        float v1=Yd[r*64+32+l]+Xs[r*64+32+l];
        float s=v0+v1;
#pragma unroll
        for(int o=16;o>=1;o>>=1)s+=__shfl_xor_sync(0xffffffffu,s,o);
        float m=s*(1.f/64.f),d0=v0-m,d1=v1-m,q=d0*d0+d1*d1;
#pragma unroll
        for(int o=16;o>=1;o>>=1)q+=__shfl_xor_sync(0xffffffffu,q,o);
        float inv=rsqrtf(q*(1.f/64.f)+LN_EPS);
        Xs[r*64+l]=d0*inv*g0+e0; Xs[r*64+32+l]=d1*inv*g1v+e1v;
    }
}

extern "C" __global__ void __launch_bounds__(256,1)
radiance_ffma(const float* __restrict__ query,const float* __restrict__ latent,
        const float* __restrict__ W1,const float* __restrict__ b1,
        const float* __restrict__ Wq,const float* __restrict__ bq,
        const float* __restrict__ Wk,const float* __restrict__ bk,
        const float* __restrict__ Wv,const float* __restrict__ bv,
        const float* __restrict__ Wo,const float* __restrict__ bo,
        const float* __restrict__ fW1,const float* __restrict__ fb1,
        const float* __restrict__ fW2,const float* __restrict__ fb2,
        const float* __restrict__ g1,const float* __restrict__ be1,
        const float* __restrict__ g2,const float* __restrict__ be2,
        const float* __restrict__ cWq,const float* __restrict__ cbq,
        const float* __restrict__ cWk,const float* __restrict__ cbk,
        const float* __restrict__ cWv,const float* __restrict__ cbv,
        const float* __restrict__ cWo,const float* __restrict__ cbo,
        const float* __restrict__ Wc,const float* __restrict__ bc,
        const float* __restrict__ Ws,const float* __restrict__ bs,
        float* __restrict__ out){
    if(*(volatile int*)&g_ok==MMA_GRID) return;
    extern __shared__ float smem[];
    float* SX=smem+F_SX; float* SCTX=smem+F_SCTX; float* ST=smem+F_ST;
    float* SW=smem+F_SW; float* SP=smem+F_SP; float* SQI=smem+F_SQI; float* SCA=smem+F_SCA;
    const int tid=threadIdx.x, w=tid>>5, l=tid&31, b0=blockIdx.x*8;
    float* attn_out=out+OFF_ATTN;

    {
        const int c0=(tid&15)*4, rb=(tid>>4)*4;
        ull a01[4]={0,0,0,0},a23[4]={0,0,0,0};
        for(int ch=0;ch<4;++ch){
            __syncthreads();
            cp_f4f(SW,W1+ch*8192,2048,tid);
            for(int i=tid;i<2048;i+=NTF){
                int r=i>>5,j=i&31;
                reinterpret_cast<float4*>(ST)[i]=
                    *reinterpret_cast<const float4*>(latent+(size_t)(b0*8+r)*512+ch*128+j*4);
            }
            __syncthreads();
            gemm_accF<128,128>(ST,SW,a01,a23,c0,rb);
        }
        float b0v=b1[c0],b1v=b1[c0+1],b2v=b1[c0+2],b3v=b1[c0+3];
#pragma unroll
        for(int r=0;r<4;++r){
            float2 v01=upk(a01[r]),v23=upk(a23[r]);
            *reinterpret_cast<float4*>(SX+(rb+r)*64+c0)=
                make_float4(fmaxf(v01.x+b0v,0.f),fmaxf(v01.y+b1v,0.f),
                            fmaxf(v23.x+b2v,0.f),fmaxf(v23.y+b3v,0.f));
        }
    }

    for(int li=0;li<4;++li){
        const float* Wq_i=Wq+li*16384; const float* Wk_i=Wk+li*16384;
        const float* Wv_i=Wv+li*16384;
        for(int h=0;h<4;++h){
            __syncthreads();
            cp_slicef(SW,Wq_i+h*64,tid);
            cp_slicef(SW+4096,Wk_i+h*64,tid);
            cp_slicef(SW+8192,Wv_i+h*64,tid);
            __syncthreads();
            gemm_blockF<64,64,false>(SX,SW,bq+li*256+h*64,ST,tid);
            gemm_blockF<64,64,false>(SX,SW+4096,bk+li*256+h*64,ST+4096,tid);
            gemm_blockF<64,64,false>(SX,SW+8192,bv+li*256+h*64,ST+8192,tid);
            __syncthreads();
            {
                const float* qB=ST+w*512; const float* kB=ST+4096+w*512; const float* vB=ST+8192+w*512;
                int qi=l>>3,kj=l&7;
                float s0=0.f,s1=0.f;
#pragma unroll 8
                for(int d=0;d<64;++d){
                    float kv=kB[kj*64+d];
                    s0+=qB[qi*64+d]*kv; s1+=qB[(qi+4)*64+d]*kv;
                }
                s0*=SC_ATT;s1*=SC_ATT;
                float m0=s0,m1=s1;
#pragma unroll
                for(int o=1;o<8;o<<=1){
                    m0=fmaxf(m0,__shfl_xor_sync(0xffffffffu,m0,o));
                    m1=fmaxf(m1,__shfl_xor_sync(0xffffffffu,m1,o));
                }
                float e0=expf(s0-m0),e1=expf(s1-m1),t0=e0,t1=e1;
#pragma unroll
                for(int o=1;o<8;o<<=1){
                    t0+=__shfl_xor_sync(0xffffffffu,t0,o);
                    t1+=__shfl_xor_sync(0xffffffffu,t1,o);
                }
                float p0=e0/t0,p1=e1/t1;
                SP[w*64+l]=p0; SP[w*64+32+l]=p1;
                size_t ab=(size_t)(b0+w)*1024+li*256+h*64;
                attn_out[ab+l]=p0; attn_out[ab+32+l]=p1;
                __syncwarp();
#pragma unroll
                for(int qq=0;qq<8;++qq){
                    float a0=0.f,a1=0.f;
#pragma unroll
                    for(int kk2=0;kk2<8;++kk2){
                        float p=SP[w*64+qq*8+kk2];
                        a0+=p*vB[kk2*64+l]; a1+=p*vB[kk2*64+32+l];
                    }
                    SCTX[(w*8+qq)*256+h*64+l]=a0;
                    SCTX[(w*8+qq)*256+h*64+32+l]=a1;
                }
            }
        }
        __syncthreads();
        cp_f4f(SW,Wo+li*16384,4096,tid);
        __syncthreads();
        gemm_blockF<256,256,false>(SCTX,SW,bo+li*64,ST,tid);
        __syncthreads();
        ln_blockF(ST,SX,g1+li*64,be1+li*64,w,l);
        __syncthreads();
        cp_f4f(SW,fW1+li*4096,1024,tid);
        cp_f4f(SW+4096,fW2+li*4096,1024,tid);
        __syncthreads();
        gemm_blockF<64,64,true>(SX,SW,fb1+li*64,ST+4096,tid);
        __syncthreads();
        gemm_blockF<64,64,false>(ST+4096,SW+4096,fb2+li*64,ST,tid);
        __syncthreads();
        ln_blockF(ST,SX,g2+li*64,be2+li*64,w,l);
    }

    for(int i=tid;i<512;i+=NTF)
        SQI[i]=query[(size_t)(b0+(i>>6))*64+(i&63)];

    for(int h=0;h<4;++h){
        __syncthreads();
        cp_slicef(SW,cWq+h*64,tid);
        cp_slicef(SW+4096,cWk+h*64,tid);
        cp_slicef(SW+8192,cWv+h*64,tid);
        __syncthreads();
        gemm_blockF<64,64,false>(SX,SW+4096,cbk+h*64,ST,tid);
        gemm_blockF<64,64,false>(SX,SW+8192,cbv+h*64,ST+4096,tid);
        for(int c=l;c<64;c+=32){
            float a=0.f;
#pragma unroll 8
            for(int k2=0;k2<64;++k2) a+=SQI[w*64+k2]*SW[k2*64+c];
            ST[8192+w*64+c]=a+cbq[h*64+c];
        }
        __syncthreads();
        {
            int j=l>>2,part=l&3;
            const float* qrow=ST+8192+w*64; const float* kB=ST+w*512;
            float sc=0.f;
#pragma unroll
            for(int d=part*16;d<part*16+16;++d) sc+=qrow[d]*kB[j*64+d];
            sc+=__shfl_xor_sync(0xffffffffu,sc,1);
            sc+=__shfl_xor_sync(0xffffffffu,sc,2);
            sc*=SC_ATT;
            if(part==0) SP[w*8+j]=sc;
            __syncwarp();
            float mx=-1e30f;
#pragma unroll
            for(int jj=0;jj<8;++jj) mx=fmaxf(mx,SP[w*8+jj]);
            float pe[8],ssum=0.f;
#pragma unroll
            for(int jj=0;jj<8;++jj){pe[jj]=expf(SP[w*8+jj]-mx);ssum+=pe[jj];}
            float inv=1.f/ssum;
            const float* vB=ST+4096+w*512;
            for(int c=l;c<64;c+=32){
                float a=0.f;
#pragma unroll
                for(int jj=0;jj<8;++jj) a+=pe[jj]*vB[jj*64+c];
                SCTX[(w*8)*256+h*64+c]=a*inv;
            }
        }
    }
    __syncthreads();
    cp_f4f(SW,cWo,4096,tid);
    __syncthreads();
    {
        const float* ctx=SCTX+w*2048;
        float a0=0.f,a1=0.f;
#pragma unroll 8
        for(int k2=0;k2<256;++k2){
            float cv=ctx[k2];
            a0+=cv*SW[k2*64+l]; a1+=cv*SW[k2*64+32+l];
        }
        a0=fmaxf(a0+cbo[l],0.f); a1=fmaxf(a1+cbo[l+32],0.f);
        SCA[w*64+l]=a0; SCA[w*64+32+l]=a1;
        __syncwarp();
#pragma unroll
        for(int cq=0;cq<3;++cq){
            float p=SCA[w*64+l]*Wc[l*3+cq]+SCA[w*64+32+l]*Wc[(l+32)*3+cq];
#pragma unroll
            for(int o=16;o>=1;o>>=1)p+=__shfl_xor_sync(0xffffffffu,p,o);
            if(l==0) out[(size_t)(b0+w)*3+cq]=p+bc[cq];
        }
        float m0=-1e30f,m1=-1e30f;
#pragma unroll
        for(int s2=0;s2<8;++s2){
            m0=fmaxf(m0,SX[(w*8+s2)*64+l]);
            m1=fmaxf(m1,SX[(w*8+s2)*64+32+l]);
        }
        float p=m0*Ws[l]+m1*Ws[l+32];
#pragma unroll
        for(int o=16;o>=1;o>>=1)p+=__shfl_xor_sync(0xffffffffu,p,o);
        if(l==0) out[OFF_SIGMA+b0+w]=p+bs[0];
    }
    for(int i=tid;i<4096;i+=NTF)
        out[OFF_OUT+(size_t)b0*512+i]=SX[i];
}

extern "C" void kernel_launch(void* const* d_in,const int* in_sizes,int n_in,
                              void* d_out,int out_size){
    (void)in_sizes;(void)n_in;(void)out_size;
    const float* query=(const float*)d_in[0];
    const float* latent=(const float*)d_in[1];
    const float* W1=(const float*)d_in[2];  const float* b1=(const float*)d_in[3];
    const float* Wq=(const float*)d_in[4];  const float* bq=(const float*)d_in[5];
    const float* Wk=(const float*)d_in[6];  const float* bk=(const float*)d_in[7];
    const float* Wv=(const float*)d_in[8];  const float* bv=(const float*)d_in[9];
    const float* Wo=(const float*)d_in[10]; const float* bo=(const float*)d_in[11];
    const float* fW1=(const float*)d_in[12];const float* fb1=(const float*)d_in[13];
    const float* fW2=(const float*)d_in[14];const float* fb2=(const float*)d_in[15];
    const float* g1=(const float*)d_in[16]; const float* be1=(const float*)d_in[17];
    const float* g2=(const float*)d_in[18]; const float* be2=(const float*)d_in[19];
    const float* cWq=(const float*)d_in[20];const float* cbq=(const float*)d_in[21];
    const float* cWk=(const float*)d_in[22];const float* cbk=(const float*)d_in[23];
    const float* cWv=(const float*)d_in[24];const float* cbv=(const float*)d_in[25];
    const float* cWo=(const float*)d_in[26];const float* cbo=(const float*)d_in[27];
    const float* Wc=(const float*)d_in[28]; const float* bc=(const float*)d_in[29];
    const float* Ws=(const float*)d_in[30]; const float* bs=(const float*)d_in[31];
    float* out=(float*)d_out;

    reset_kernel<<<1,1>>>();
    prep_kernel<<<(88*4096+255)/256,256>>>(W1,Wq,Wk,Wv,Wo,fW1,fW2,cWk,cWv);

    const int smem_mma=27664*sizeof(float);
    cudaFuncSetAttribute(radiance_mma,cudaFuncAttributeMaxDynamicSharedMemorySize,smem_mma);
    radiance_mma<<<MMA_GRID,512,smem_mma>>>(query,latent,b1,bq,bk,bv,bo,fb1,fb2,
        g1,be1,g2,be2,cWq,cbq,cbk,cbv,cWo,cbo,Wc,bc,Ws,bs,out);

    const int smem_ffma=F_SMEMF*sizeof(float);
    cudaFuncSetAttribute(radiance_ffma,cudaFuncAttributeMaxDynamicSharedMemorySize,smem_ffma);
    radiance_ffma<<<BB/8,256,smem_ffma>>>(query,latent,W1,b1,Wq,bq,Wk,bk,Wv,bv,Wo,bo,
        fW1,fb1,fW2,fb2,g1,be1,g2,be2,cWq,cbq,cWk,cbk,cWv,cbv,cWo,cbo,Wc,bc,Ws,bs,out);
}

// round 15
// speedup vs baseline: 1.4911x; 1.0003x over previous
#include <cuda_runtime.h>
#include <cuda_bf16.h>
#include <stdint.h>
#include <math.h>

#if defined(__CUDA_ARCH_FEAT_SM103_ALL) || defined(__CUDA_ARCH_FEAT_SM100_ALL) || defined(__CUDA_ARCH_FEAT_SM101_ALL)
#define HAS_TC 1
#else
#define HAS_TC 0
#endif

#define BB 32768
#define LN_EPS 1e-5f
#define SC_ATT 0.125f
#define OFF_SIGMA (3*BB)
#define OFF_OUT (OFF_SIGMA+BB)
#define OFF_ATTN (OFF_OUT+(size_t)BB*512)
#define MMA_GRID 2048

__device__ __nv_bfloat16 g_Bh[88*8192];   // per tile: 4096 hi then 4096 lo
__device__ int g_ok;

extern "C" __global__ void reset_kernel(){ g_ok = 0; }

__device__ __forceinline__ int axAf(int m,int k){return ((k>>5)<<12)|((m>>3)<<8)|((m&7)<<5)|((k&31)^((m&7)<<2));}
__device__ __forceinline__ int axHb(int r,int k){
    int byte=(r&7)*128+k*2; byte^=((byte>>3)&0x70);
    return ((r>>3)<<9)+(byte>>1);
}
__device__ __forceinline__ void sp2b(float v,__nv_bfloat16&h,__nv_bfloat16&l){
    h=__float2bfloat16(v); l=__float2bfloat16(v-(float)h);
}

extern "C" __global__ void prep_kernel(const float* W1,const float* Wq,const float* Wk,const float* Wv,
        const float* Wo,const float* fW1,const float* fW2,const float* cWk,const float* cWv){
    int idx=blockIdx.x*256+threadIdx.x;
    if(idx>=88*4096)return;
    int tile=idx>>12,j=idx&4095,n=j>>6,k=j&63;
    float v;
    if(tile<8) v=W1[(tile*64+k)*64+n];
    else if(tile<56){int t=tile-8,lh=t/3,wch=t%3,li=lh>>2,h=lh&3;
        const float* W=(wch==0)?Wq:((wch==1)?Wk:Wv);
        v=W[li*16384+k*256+h*64+n];}
    else if(tile<72){int t=tile-56,li=t>>2,h=t&3; v=Wo[li*16384+(h*64+k)*64+n];}
    else if(tile<80){int t=tile-72,li=t>>1; v=((t&1)?fW2:fW1)[li*4096+k*64+n];}
    else if(tile<84) v=cWk[k*256+(tile-80)*64+n];
    else v=cWv[k*256+(tile-84)*64+n];
    __nv_bfloat16 h,l; sp2b(v,h,l);
    int ax=axHb(n,k);
    g_Bh[(size_t)tile*8192+ax]=h;
    g_Bh[(size_t)tile*8192+4096+ax]=l;
}

#if HAS_TC
#define NTM 512
#define IDESC 0x8100490u
#define O_XH 0
#define O_XL 4096
#define O_R0 8192
#define O_R1 12288
#define O_R2 16384
#define O_R3 20480
#define O_SP 24576
#define O_QC 25600
#define O_SQI 26624
#define O_CTL 27648
#define SMEMF 27664

__device__ __forceinline__ uint32_t s2u(const void* p){
    uint32_t a; asm("{.reg .u64 t; cvta.to.shared.u64 t,%1; cvt.u32.u64 %0,t;}":"=r"(a):"l"(p)); return a;
}
__device__ __forceinline__ uint32_t elect1(){
    uint32_t r; asm volatile("{.reg .pred p; elect.sync _|p,0xFFFFFFFF; selp.b32 %0,1,0,p;}":"=r"(r)); return r;
}
__device__ __forceinline__ uint64_t sdesc(uint32_t a){
    const uint64_t b=(uint64_t(2)<<61)|(uint64_t(1)<<46)|(uint64_t(64)<<32)|(uint64_t(1)<<16);
    return b|((a>>4)&0x3FFFu);
}
__device__ __forceinline__ void mma1(uint32_t d,uint64_t ad,uint64_t bd,uint32_t en){
    asm volatile("{.reg .pred p; setp.ne.u32 p,%4,0;\n\t"
        "tcgen05.mma.cta_group::1.kind::f16 [%0],%1,%2,%3,{%5,%5,%5,%5},p;}"
        ::"r"(d),"l"(ad),"l"(bd),"r"(IDESC),"r"(en),"r"(0u):"memory");
}
__device__ __forceinline__ void mma_k64b(uint32_t d,uint32_t a_s,uint32_t b_s,bool acc){
    uint64_t ad=sdesc(a_s),bd=sdesc(b_s);
#pragma unroll
    for(int s=0;s<4;++s)
        mma1(d,ad+(uint32_t)(s*2),bd+(uint32_t)(s*2),(acc||s>0)?1u:0u);
}
__device__ __forceinline__ void mma3b(uint32_t d,uint32_t ah,uint32_t al,uint32_t bh,uint32_t bl,bool acc){
    mma_k64b(d,ah,bh,acc);
    mma_k64b(d,al,bh,true);
    mma_k64b(d,ah,bl,true);
}
#define TCOMMIT(mb) asm volatile("tcgen05.commit.cta_group::1.mbarrier::arrive::one.shared::cluster.b64 [%0];"::"r"(mb):"memory")
#define FPA() asm volatile("fence.proxy.async.shared::cta;":::"memory")
#define TFA() asm volatile("tcgen05.fence::after_thread_sync;":::"memory")
#define TFB() asm volatile("tcgen05.fence::before_thread_sync;":::"memory")

// sleeping bounded wait: HW TRYWAIT with suspend hint (no hot spin)
__device__ __forceinline__ bool mb_poll(uint32_t mb,uint32_t par){
    for(int i=0;i<40000;++i){
        uint32_t d;
        asm volatile("{.reg .pred P; mbarrier.try_wait.parity.acquire.cta.shared::cta.b64 P,[%1],%2,0x989680; selp.b32 %0,1,0,P;}"
            :"=r"(d):"r"(mb),"r"(par):"memory");
        if(d) return true;
    }
    return false;
}
__device__ __forceinline__ void ldtm16(uint32_t t,float* f){
    uint32_t r[16];
    asm volatile("tcgen05.ld.sync.aligned.32x32b.x16.b32 {%0,%1,%2,%3,%4,%5,%6,%7,%8,%9,%10,%11,%12,%13,%14,%15},[%16];"
        :"=r"(r[0]),"=r"(r[1]),"=r"(r[2]),"=r"(r[3]),"=r"(r[4]),"=r"(r[5]),"=r"(r[6]),"=r"(r[7]),
         "=r"(r[8]),"=r"(r[9]),"=r"(r[10]),"=r"(r[11]),"=r"(r[12]),"=r"(r[13]),"=r"(r[14]),"=r"(r[15])
        :"r"(t));
    asm volatile("tcgen05.wait::ld.sync.aligned;":::"memory");
#pragma unroll
    for(int i=0;i<16;++i) f[i]=__uint_as_float(r[i]);
}
__device__ __forceinline__ void epi_fullf(uint32_t t,const float* bias,float* X,int m_r,int c0){
    float r[16]; ldtm16(t,r);
#pragma unroll
    for(int i=0;i<16;i+=4){
        float4 v=make_float4(r[i]+bias[i],r[i+1]+bias[i+1],r[i+2]+bias[i+2],r[i+3]+bias[i+3]);
        *reinterpret_cast<float4*>(X+axAf(m_r,c0+i))=v;
    }
}
__device__ __forceinline__ void epi_splitb(uint32_t t,const float* bias,
        __nv_bfloat16* Hb,__nv_bfloat16* Lb,int m_r,int c0,bool relu){
    float r[16]; ldtm16(t,r);
#pragma unroll
    for(int j=0;j<8;++j){
        float v0=r[2*j]+bias[2*j], v1=r[2*j+1]+bias[2*j+1];
        if(relu){v0=fmaxf(v0,0.f);v1=fmaxf(v1,0.f);}
        __nv_bfloat16 h0,l0,h1,l1;
        sp2b(v0,h0,l0); sp2b(v1,h1,l1);
        int k=c0+2*j;
        int byte=(m_r&7)*128+k*2; byte^=((byte>>3)&0x70);
        int base=((m_r>>3)<<10)+byte;
        __nv_bfloat162 hp; hp.x=h0; hp.y=h1;
        __nv_bfloat162 lp; lp.x=l0; lp.y=l1;
        *reinterpret_cast<__nv_bfloat162*>(reinterpret_cast<char*>(Hb)+base)=hp;
        *reinterpret_cast<__nv_bfloat162*>(reinterpret_cast<char*>(Lb)+base)=lp;
    }
}
__device__ __forceinline__ void cp_f4m(float* d,const float* s,int n4,int tid){
    for(int i=tid;i<n4;i+=NTM) reinterpret_cast<float4*>(d)[i]=reinterpret_cast<const float4*>(s)[i];
}
__device__ __forceinline__ void cp_pair(float* dst,int tile,int tid){
    const float4* s=reinterpret_cast<const float4*>(g_Bh+(size_t)tile*8192);
    for(int i=tid;i<1024;i+=NTM) reinterpret_cast<float4*>(dst)[i]=s[i];
}
__device__ __forceinline__ void cp_slicem(float* d,const float* s,int tid){
    for(int i=tid;i<1024;i+=NTM){int r=i>>4,c=i&15;
        reinterpret_cast<float4*>(d)[i]=reinterpret_cast<const float4*>(s+r*256)[c];}
}
__device__ __forceinline__ void ln_b(const float* Y,__nv_bfloat16* XHb,__nv_bfloat16* XLb,
        const float* g,const float* be,int w,int l){
    float g0=g[l],g1v=g[l+32],e0=be[l],e1v=be[l+32];
#pragma unroll
    for(int i=0;i<8;++i){
        int r=w*8+i;
        int y0=axAf(r,l), y1=axAf(r,l+32);
        int b0i=axHb(r,l), b1i=axHb(r,l+32);
        float v0=Y[y0]+(float)XHb[b0i]+(float)XLb[b0i];
        float v1=Y[y1]+(float)XHb[b1i]+(float)XLb[b1i];
        float s=v0+v1;
#pragma unroll
        for(int o=16;o>=1;o>>=1)s+=__shfl_xor_sync(0xffffffffu,s,o);
        float m=s*(1.f/64.f),d0=v0-m,d1=v1-m,q=d0*d0+d1*d1;
#pragma unroll
        for(int o=16;o>=1;o>>=1)q+=__shfl_xor_sync(0xffffffffu,q,o);
        float inv=rsqrtf(q*(1.f/64.f)+LN_EPS);
        float a=d0*inv*g0+e0, b=d1*inv*g1v+e1v;
        sp2b(a,XHb[b0i],XLb[b0i]);
        sp2b(b,XHb[b1i],XLb[b1i]);
    }
}
#define WAITX do{ \
    if(tid==0){ if(SOK[0] && !mb_poll(mbv[wc&1],(uint32_t)((wc>>1)&1))) SOK[0]=0; } \
    __syncthreads(); \
    wc++; }while(0)
#endif

extern "C" __global__ void __launch_bounds__(512,2)
#if HAS_TC
__cluster_dims__(1,1,1)
#endif
radiance_mma(const float* __restrict__ query,const float* __restrict__ latent,
        const float* __restrict__ b1,const float* __restrict__ bq,const float* __restrict__ bk,
        const float* __restrict__ bv,const float* __restrict__ bo,const float* __restrict__ fb1,
        const float* __restrict__ fb2,const float* __restrict__ g1,const float* __restrict__ be1,
        const float* __restrict__ g2,const float* __restrict__ be2,const float* __restrict__ cWq,
        const float* __restrict__ cbq,const float* __restrict__ cbk,const float* __restrict__ cbv,
        const float* __restrict__ cWo,const float* __restrict__ cbo,const float* __restrict__ Wc,
        const float* __restrict__ bc,const float* __restrict__ Ws,const float* __restrict__ bs,
        float* __restrict__ out){
#if HAS_TC
    extern __shared__ float smem[];
    float* R0f=smem+O_R0; float* R1f=smem+O_R1; float* R2f=smem+O_R2; float* R3f=smem+O_R3;
    __nv_bfloat16* XHb=reinterpret_cast<__nv_bfloat16*>(smem+O_XH);
    __nv_bfloat16* XLb=reinterpret_cast<__nv_bfloat16*>(smem+O_XL);
    float* SP=smem+O_SP; float* QC=smem+O_QC; float* SQI=smem+O_SQI;
    volatile int* SOK=reinterpret_cast<volatile int*>(smem+O_CTL+6);
    const int tid=threadIdx.x,wid=tid>>5,l=tid&31,w=wid;
    const int b0=blockIdx.x*16;
    const int m_r=(wid&3)*32+l, c0=(wid>>2)*16;
    uint32_t sb=s2u(smem), ctl=sb+O_CTL*4;
    uint32_t mbv[2]={ctl+8,ctl+16};
    int cc=0, wc=0; (void)cc;

    if(tid==0){
        asm volatile("mbarrier.init.shared.b64 [%0],1;"::"r"(mbv[0]):"memory");
        asm volatile("mbarrier.init.shared.b64 [%0],1;"::"r"(mbv[1]):"memory");
        SOK[0]=1;
    }
    if(wid==0){
        asm volatile("tcgen05.alloc.cta_group::1.sync.aligned.shared::cta.b32 [%0],%1;"::"r"(ctl),"r"(256u):"memory");
        asm volatile("tcgen05.relinquish_alloc_permit.cta_group::1.sync.aligned;");
    }
    FPA(); __syncthreads();
    uint32_t tb; asm("ld.shared.b32 %0,[%1];":"=r"(tb):"r"(ctl));
    const uint32_t DQ=tb,DK=tb+64,DV=tb+128,DO=tb+192;
    const uint32_t aXH=sb+O_XH*4,aXL=sb+O_XL*4;
    const uint32_t aR0=sb+O_R0*4,aR1=sb+O_R1*4,aR2=sb+O_R2*4,aR3=sb+O_R3*4;
    float* attn_out=out+OFF_ATTN;

    // ======== stage0: X = relu(latent@W1+b1), K=512 in 8 chunks ========
    for(int ch=0;ch<8;++ch){
        if(ch>=2) WAITX;
        __nv_bfloat16* Ah=reinterpret_cast<__nv_bfloat16*>((ch&1)?R2f:R0f);
        __nv_bfloat16* Al=reinterpret_cast<__nv_bfloat16*>((ch&1)?R3f:R1f);
        float* Bp=(ch&1)?(smem+O_XL):(smem+O_XH);
        uint32_t aAh=(ch&1)?aR2:aR0, aAl=(ch&1)?aR3:aR1;
        uint32_t aBp=(ch&1)?aXL:aXH;
        for(int i=tid;i<2048;i+=NTM){
            int m=i>>4,k4=(i&15)<<2;
            float4 v=*reinterpret_cast<const float4*>(latent+(size_t)(b0*8+m)*512+ch*64+k4);
            __nv_bfloat16 h0,l0,h1,l1,h2,l2,h3,l3;
            sp2b(v.x,h0,l0); sp2b(v.y,h1,l1); sp2b(v.z,h2,l2); sp2b(v.w,h3,l3);
            int byte=(m&7)*128+k4*2; byte^=((byte>>3)&0x70);
            int base=((m>>3)<<10)+byte;
            __nv_bfloat162 p01h; p01h.x=h0; p01h.y=h1;
            __nv_bfloat162 p23h; p23h.x=h2; p23h.y=h3;
            __nv_bfloat162 p01l; p01l.x=l0; p01l.y=l1;
            __nv_bfloat162 p23l; p23l.x=l2; p23l.y=l3;
            *reinterpret_cast<__nv_bfloat162*>(reinterpret_cast<char*>(Ah)+base)=p01h;
            *reinterpret_cast<__nv_bfloat162*>(reinterpret_cast<char*>(Ah)+base+4)=p23h;
            *reinterpret_cast<__nv_bfloat162*>(reinterpret_cast<char*>(Al)+base)=p01l;
            *reinterpret_cast<__nv_bfloat162*>(reinterpret_cast<char*>(Al)+base+4)=p23l;
        }
        cp_pair(Bp,ch,tid);
        FPA(); __syncthreads();
        if(wid==0){ TFA();
            if(elect1()){
                mma3b(DQ,aAh,aAl,aBp,aBp+8192,ch>0);
                TCOMMIT(mbv[cc&1]);
            }
        }
        cc++;
    }
    WAITX; WAITX;
    TFA();
    epi_splitb(DQ+c0,b1+c0,XHb,XLb,m_r,c0,true);
    TFB(); FPA(); __syncthreads();

    // ======== 4 transformer layers ========
    for(int li=0;li<4;++li){
        for(int h=0;h<4;++h){
            if(h>0) WAITX;                 // O-mma(h-1)
            int base=8+(li*4+h)*3;
            cp_pair(R0f,base,tid);         // Bq pair
            cp_pair(R1f,base+1,tid);       // Bk pair
            cp_pair(R2f,base+2,tid);       // Bv pair
            FPA(); __syncthreads();
            if(wid==0){ TFA();
                if(elect1()){
                    mma3b(DQ,aXH,aXL,aR0,aR0+8192,false);
                    mma3b(DK,aXH,aXL,aR1,aR1+8192,false);
                    mma3b(DV,aXH,aXL,aR2,aR2+8192,false);
                    TCOMMIT(mbv[cc&1]);
                }
            }
            cc++;
            WAITX;
            TFA();
            epi_fullf(DQ+c0,bq+li*256+h*64+c0,R0f,m_r,c0);   // Q fp32 -> R0R1
            epi_fullf(DK+c0,bk+li*256+h*64+c0,R2f,m_r,c0);   // K fp32 -> R2R3
            TFB();
            __syncthreads();
            {   // scores per warp (= batch), fp32
                const int qi=l>>3,kj=l&7;
                float s0=0.f,s1=0.f;
#pragma unroll
                for(int d4=0;d4<64;d4+=4){
                    float4 kv=*reinterpret_cast<const float4*>(R2f+axAf(w*8+kj,d4));
                    float4 q0=*reinterpret_cast<const float4*>(R0f+axAf(w*8+qi,d4));
                    float4 q1=*reinterpret_cast<const float4*>(R0f+axAf(w*8+qi+4,d4));
                    s0+=q0.x*kv.x+q0.y*kv.y+q0.z*kv.z+q0.w*kv.w;
                    s1+=q1.x*kv.x+q1.y*kv.y+q1.z*kv.z+q1.w*kv.w;
                }
                s0*=SC_ATT;s1*=SC_ATT;
                float m0=s0,m1=s1;
#pragma unroll
                for(int o=1;o<8;o<<=1){
                    m0=fmaxf(m0,__shfl_xor_sync(0xffffffffu,m0,o));
                    m1=fmaxf(m1,__shfl_xor_sync(0xffffffffu,m1,o));
                }
                float e0=__expf(s0-m0),e1=__expf(s1-m1),t0=e0,t1=e1;
#pragma unroll
                for(int o=1;o<8;o<<=1){
                    t0+=__shfl_xor_sync(0xffffffffu,t0,o);
                    t1+=__shfl_xor_sync(0xffffffffu,t1,o);
                }
                float p0=e0/t0,p1=e1/t1;
                SP[w*64+l]=p0; SP[w*64+32+l]=p1;
                size_t ab=(size_t)(b0+w)*1024+li*256+h*64;
                attn_out[ab+l]=p0; attn_out[ab+32+l]=p1;
            }
            __syncthreads();               // all warps done with Q (R0R1)
            TFA();
            epi_fullf(DV+c0,bv+li*256+h*64+c0,R0f,m_r,c0);   // V fp32 -> R0R1
            TFB();
            __syncthreads();
            {   // ctx = P@V ; split bf16 pair into R2(hi)/R3(lo) (K dead)
                float a0[8],a1[8];
#pragma unroll
                for(int q2=0;q2<8;++q2){a0[q2]=0.f;a1[q2]=0.f;}
#pragma unroll
                for(int kk=0;kk<8;++kk){
                    float v0=R0f[axAf(w*8+kk,l)],v1=R0f[axAf(w*8+kk,l+32)];
#pragma unroll
                    for(int q2=0;q2<8;++q2){
                        float p=SP[w*64+q2*8+kk];
                        a0[q2]+=p*v0; a1[q2]+=p*v1;
                    }
                }
                __nv_bfloat16* CH=reinterpret_cast<__nv_bfloat16*>(R2f);
                __nv_bfloat16* CL=reinterpret_cast<__nv_bfloat16*>(R3f);
#pragma unroll
                for(int q2=0;q2<8;++q2){
                    int i0=axHb(w*8+q2,l), i1=axHb(w*8+q2,l+32);
                    sp2b(a0[q2],CH[i0],CL[i0]);
                    sp2b(a1[q2],CH[i1],CL[i1]);
                }
            }
            FPA(); __syncthreads();        // ctx visible; V dead
            cp_pair(R0f,56+li*4+h,tid);    // Wo pair
            FPA(); __syncthreads();
            if(wid==0){ TFA();
                if(elect1()){ mma3b(DO,aR2,aR3,aR0,aR0+8192,h>0); TCOMMIT(mbv[cc&1]); }
            }
            cc++;
        } // heads
        WAITX;
        TFA();
        epi_fullf(DO+c0,bo+li*64+c0,R0f,m_r,c0);    // Y fp32 -> R0R1
        TFB(); __syncthreads();
        ln_b(R0f,XHb,XLb,g1+li*64,be1+li*64,w,l);
        cp_pair(R2f,72+li*2,tid);                   // fW1 pair
        cp_pair(R3f,73+li*2,tid);                   // fW2 pair
        FPA(); __syncthreads();
        if(wid==0){ TFA();
            if(elect1()){ mma3b(DQ,aXH,aXL,aR2,aR2+8192,false); TCOMMIT(mbv[cc&1]); }
        }
        cc++;
        WAITX;
        TFA();
        epi_splitb(DQ+c0,fb1+li*64+c0,
                   reinterpret_cast<__nv_bfloat16*>(R0f),
                   reinterpret_cast<__nv_bfloat16*>(R1f),m_r,c0,true);  // h1 pair
        TFB(); FPA(); __syncthreads();
        if(wid==0){ TFA();
            if(elect1()){ mma3b(DK,aR0,aR1,aR3,aR3+8192,false); TCOMMIT(mbv[cc&1]); }
        }
        cc++;
        WAITX;
        TFA();
        epi_fullf(DK+c0,fb2+li*64+c0,R2f,m_r,c0);   // Y2 fp32 -> R2R3
        TFB(); __syncthreads();
        ln_b(R2f,XHb,XLb,g2+li*64,be2+li*64,w,l);
        FPA(); __syncthreads();
    } // layers

    // ======== cross attention ========
    for(int i=tid;i<1024;i+=NTM) SQI[i]=query[(size_t)(b0+(i>>6))*64+(i&63)];
    float ca0=0.f,ca1=0.f;
    for(int h=0;h<4;++h){
        cp_pair(R0f,80+h,tid);
        cp_pair(R1f,84+h,tid);
        cp_slicem(R2f,cWq+h*64,tid);
        cp_f4m(R3f,cWo+h*4096,1024,tid);
        FPA(); __syncthreads();
        if(wid==0){ TFA();
            if(elect1()){
                mma3b(DQ,aXH,aXL,aR0,aR0+8192,false);   // Kc
                mma3b(DK,aXH,aXL,aR1,aR1+8192,false);   // Vc
                TCOMMIT(mbv[cc&1]);
            }
        }
        cc++;
        for(int c=l;c<64;c+=32){
            float a=0.f;
#pragma unroll 8
            for(int k2=0;k2<64;++k2) a+=SQI[w*64+k2]*R2f[k2*64+c];
            QC[w*64+c]=a+cbq[h*64+c];
        }
        __syncwarp();
        WAITX;
        TFA();
        epi_fullf(DQ+c0,cbk+h*64+c0,R0f,m_r,c0);    // Kc fp32 -> R0R1
        TFB();
        __syncthreads();
        {
            const int j=l>>2,part=l&3;
            float sc=0.f;
#pragma unroll
            for(int d4=part*16;d4<part*16+16;d4+=4){
                float4 kv=*reinterpret_cast<const float4*>(R0f+axAf(w*8+j,d4));
                sc+=QC[w*64+d4]*kv.x+QC[w*64+d4+1]*kv.y+QC[w*64+d4+2]*kv.z+QC[w*64+d4+3]*kv.w;
            }
            sc+=__shfl_xor_sync(0xffffffffu,sc,1);
            sc+=__shfl_xor_sync(0xffffffffu,sc,2);
            sc*=SC_ATT;
            if(part==0) SP[w*64+j]=sc;
        }
        __syncthreads();
        TFA();
        epi_fullf(DK+c0,cbv+h*64+c0,R0f,m_r,c0);    // Vc fp32 -> R0R1
        TFB();
        __syncthreads();
        {
            float mx=-1e30f;
#pragma unroll
            for(int jj=0;jj<8;++jj) mx=fmaxf(mx,SP[w*64+jj]);
            float pe[8],ss=0.f;
#pragma unroll
            for(int jj=0;jj<8;++jj){pe[jj]=__expf(SP[w*64+jj]-mx);ss+=pe[jj];}
            float inv=1.f/ss;
            for(int c=l;c<64;c+=32){
                float a=0.f;
#pragma unroll
                for(int jj=0;jj<8;++jj) a+=pe[jj]*R0f[axAf(w*8+jj,c)];
                QC[w*64+c]=a*inv;
            }
            __syncwarp();
#pragma unroll 8
            for(int k2=0;k2<64;++k2){
                float cv=QC[w*64+k2];
                ca0+=cv*R3f[k2*64+l];
                ca1+=cv*R3f[k2*64+32+l];
            }
        }
        __syncthreads();
    }
    // ======== heads: color, sigma, out ========
    {
        float a0=fmaxf(ca0+cbo[l],0.f),a1=fmaxf(ca1+cbo[l+32],0.f);
#pragma unroll
        for(int cq=0;cq<3;++cq){
            float p=a0*Wc[l*3+cq]+a1*Wc[(l+32)*3+cq];
#pragma unroll
            for(int o=16;o>=1;o>>=1)p+=__shfl_xor_sync(0xffffffffu,p,o);
            if(l==0) out[(size_t)(b0+w)*3+cq]=p+bc[cq];
        }
        float m0=-1e30f,m1=-1e30f;
#pragma unroll
        for(int s2=0;s2<8;++s2){
            int i0=axHb(w*8+s2,l), i1=axHb(w*8+s2,l+32);
            m0=fmaxf(m0,(float)XHb[i0]+(float)XLb[i0]);
            m1=fmaxf(m1,(float)XHb[i1]+(float)XLb[i1]);
        }
        float p=m0*Ws[l]+m1*Ws[l+32];
#pragma unroll
        for(int o=16;o>=1;o>>=1)p+=__shfl_xor_sync(0xffffffffu,p,o);
        if(l==0) out[OFF_SIGMA+b0+w]=p+bs[0];
    }
    for(int i=tid;i<8192;i+=NTM){
        int ix=axHb(i>>6,i&63);
        out[OFF_OUT+(size_t)b0*512+i]=(float)XHb[ix]+(float)XLb[ix];
    }

    __syncthreads();
    if(wid==0)
        asm volatile("tcgen05.dealloc.cta_group::1.sync.aligned.b32 %0,%1;"::"r"(tb),"r"(256u));

    __syncthreads();
    if(tid==0&&SOK[0]) atomicAdd(&g_ok,1);
#else
    (void)query;(void)latent;(void)b1;(void)bq;(void)bk;(void)bv;(void)bo;(void)fb1;(void)fb2;
    (void)g1;(void)be1;(void)g2;(void)be2;(void)cWq;(void)cbq;(void)cbk;(void)cbv;(void)cWo;
    (void)cbo;(void)Wc;(void)bc;(void)Ws;(void)bs;(void)out;
#endif
}

// =====================================================================
//  FFMA fallback — early-exits when MMA path fully succeeded
// =====================================================================
#define NTF 256
#define F_SX   0
#define F_SCTX 4096
#define F_ST   (4096+16384)
#define F_SW   (F_ST+12288)
#define F_SP   (F_SW+16384)
#define F_SQI  (F_SP+512)
#define F_SCA  (F_SQI+512)
#define F_SMEMF 50688

typedef unsigned long long ull;
__device__ __forceinline__ ull pk2(float lo,float hi){
    ull r; asm("mov.b64 %0,{%1,%2};":"=l"(r):"r"(__float_as_uint(lo)),"r"(__float_as_uint(hi))); return r;
}
__device__ __forceinline__ void fma2(ull &a,ull b,ull c){
    asm("fma.rn.f32x2 %0,%1,%2,%0;":"+l"(a):"l"(b),"l"(c));
}
__device__ __forceinline__ float2 upk(ull v){
    unsigned lo,hi; asm("mov.b64 {%0,%1},%2;":"=r"(lo),"=r"(hi):"l"(v));
    return make_float2(__uint_as_float(lo),__uint_as_float(hi));
}
__device__ __forceinline__ void cp_f4f(float* d,const float* s,int n4,int tid){
    for(int i=tid;i<n4;i+=NTF) reinterpret_cast<float4*>(d)[i]=reinterpret_cast<const float4*>(s)[i];
}
__device__ __forceinline__ void cp_slicef(float* d,const float* s,int tid){
    for(int i=tid;i<1024;i+=NTF){int r=i>>4,c=i&15;
        reinterpret_cast<float4*>(d)[i]=reinterpret_cast<const float4*>(s+r*256)[c];}
}
template<int K,int LDX>
__device__ __forceinline__ void gemm_accF(const float* X,const float* W,ull a01[4],ull a23[4],int c0,int rb){
#pragma unroll 8
    for(int k=0;k<K;++k){
        float4 wv=*reinterpret_cast<const float4*>(W+k*64+c0);
        ull w01=pk2(wv.x,wv.y),w23=pk2(wv.z,wv.w);
#pragma unroll
        for(int r=0;r<4;++r){
            float xv=X[(rb+r)*LDX+k];
            ull xx=pk2(xv,xv);
            fma2(a01[r],w01,xx); fma2(a23[r],w23,xx);
        }
    }
}
template<int K,int LDX,bool RELU>
__device__ __forceinline__ void gemm_blockF(const float* X,const float* W,const float* bias,float* Y,int tid){
    const int c0=(tid&15)*4, rb=(tid>>4)*4;
    ull a01[4]={0,0,0,0},a23[4]={0,0,0,0};
    gemm_accF<K,LDX>(X,W,a01,a23,c0,rb);
    float b0v=bias[c0],b1v=bias[c0+1],b2v=bias[c0+2],b3v=bias[c0+3];
#pragma unroll
    for(int r=0;r<4;++r){
        float2 v01=upk(a01[r]),v23=upk(a23[r]);
        float o0=v01.x+b0v,o1=v01.y+b1v,o2=v23.x+b2v,o3=v23.y+b3v;
        if(RELU){o0=fmaxf(o0,0.f);o1=fmaxf(o1,0.f);o2=fmaxf(o2,0.f);o3=fmaxf(o3,0.f);}
        *reinterpret_cast<float4*>(Y+(rb+r)*64+c0)=make_float4(o0,o1,o2,o3);
    }
}
__device__ __forceinline__ void ln_blockF(const float* Yd,float* Xs,const float* g,const float* be,int w,int l){
    float g0=g[l],g1v=g[l+32],e0=be[l],e1v=be[l+32];
#pragma unroll
    for(int i=0;i<8;++i){
        int r=w*8+i;
        float v0=Yd[r*64+l]+Xs[r*64+l];
        float v1=Yd[r*64+32+l]+Xs[r*64+32+l];
        float s=v0+v1;
#pragma unroll
        for(int o=16;o>=1;o>>=1)s+=__shfl_xor_sync(0xffffffffu,s,o);
        float m=s*(1.f/64.f),d0=v0-m,d1=v1-m,q=d0*d0+d1*d1;
#pragma unroll
        for(int o=16;o>=1;o>>=1)q+=__shfl_xor_sync(0xffffffffu,q,o);
        float inv=rsqrtf(q*(1.f/64.f)+LN_EPS);
        Xs[r*64+l]=d0*inv*g0+e0; Xs[r*64+32+l]=d1*inv*g1v+e1v;
    }
}

extern "C" __global__ void __launch_bounds__(256,1)
radiance_ffma(const float* __restrict__ query,const float* __restrict__ latent,
        const float* __restrict__ W1,const float* __restrict__ b1,
        const float* __restrict__ Wq,const float* __restrict__ bq,
        const float* __restrict__ Wk,const float* __restrict__ bk,
        const float* __restrict__ Wv,const float* __restrict__ bv,
        const float* __restrict__ Wo,const float* __restrict__ bo,
        const float* __restrict__ fW1,const float* __restrict__ fb1,
        const float* __restrict__ fW2,const float* __restrict__ fb2,
        const float* __restrict__ g1,const float* __restrict__ be1,
        const float* __restrict__ g2,const float* __restrict__ be2,
        const float* __restrict__ cWq,const float* __restrict__ cbq,
        const float* __restrict__ cWk,const float* __restrict__ cbk,
        const float* __restrict__ cWv,const float* __restrict__ cbv,
        const float* __restrict__ cWo,const float* __restrict__ cbo,
        const float* __restrict__ Wc,const float* __restrict__ bc,
        const float* __restrict__ Ws,const float* __restrict__ bs,
        float* __restrict__ out){
    if(*(volatile int*)&g_ok==MMA_GRID) return;
    extern __shared__ float smem[];
    float* SX=smem+F_SX; float* SCTX=smem+F_SCTX; float* ST=smem+F_ST;
    float* SW=smem+F_SW; float* SP=smem+F_SP; float* SQI=smem+F_SQI; float* SCA=smem+F_SCA;
    const int tid=threadIdx.x, w=tid>>5, l=tid&31, b0=blockIdx.x*8;
    float* attn_out=out+OFF_ATTN;

    {
        const int c0=(tid&15)*4, rb=(tid>>4)*4;
        ull a01[4]={0,0,0,0},a23[4]={0,0,0,0};
        for(int ch=0;ch<4;++ch){
            __syncthreads();
            cp_f4f(SW,W1+ch*8192,2048,tid);
            for(int i=tid;i<2048;i+=NTF){
                int r=i>>5,j=i&31;
                reinterpret_cast<float4*>(ST)[i]=
                    *reinterpret_cast<const float4*>(latent+(size_t)(b0*8+r)*512+ch*128+j*4);
            }
            __syncthreads();
            gemm_accF<128,128>(ST,SW,a01,a23,c0,rb);
        }
        float b0v=b1[c0],b1v=b1[c0+1],b2v=b1[c0+2],b3v=b1[c0+3];
#pragma unroll
        for(int r=0;r<4;++r){
            float2 v01=upk(a01[r]),v23=upk(a23[r]);
            *reinterpret_cast<float4*>(SX+(rb+r)*64+c0)=
                make_float4(fmaxf(v01.x+b0v,0.f),fmaxf(v01.y+b1v,0.f),
                            fmaxf(v23.x+b2v,0.f),fmaxf(v23.y+b3v,0.f));
        }
    }

    for(int li=0;li<4;++li){
        const float* Wq_i=Wq+li*16384; const float* Wk_i=Wk+li*16384;
        const float* Wv_i=Wv+li*16384;
        for(int h=0;h<4;++h){
            __syncthreads();
            cp_slicef(SW,Wq_i+h*64,tid);
            cp_slicef(SW+4096,Wk_i+h*64,tid);
            cp_slicef(SW+8192,Wv_i+h*64,tid);
            __syncthreads();
            gemm_blockF<64,64,false>(SX,SW,bq+li*256+h*64,ST,tid);
            gemm_blockF<64,64,false>(SX,SW+4096,bk+li*256+h*64,ST+4096,tid);
            gemm_blockF<64,64,false>(SX,SW+8192,bv+li*256+h*64,ST+8192,tid);
            __syncthreads();
            {
                const float* qB=ST+w*512; const float* kB=ST+4096+w*512; const float* vB=ST+8192+w*512;
                int qi=l>>3,kj=l&7;
                float s0=0.f,s1=0.f;
#pragma unroll 8
                for(int d=0;d<64;++d){
                    float kv=kB[kj*64+d];
                    s0+=qB[qi*64+d]*kv; s1+=qB[(qi+4)*64+d]*kv;
                }
                s0*=SC_ATT;s1*=SC_ATT;
                float m0=s0,m1=s1;
#pragma unroll
                for(int o=1;o<8;o<<=1){
                    m0=fmaxf(m0,__shfl_xor_sync(0xffffffffu,m0,o));
                    m1=fmaxf(m1,__shfl_xor_sync(0xffffffffu,m1,o));
                }
                float e0=expf(s0-m0),e1=expf(s1-m1),t0=e0,t1=e1;
#pragma unroll
                for(int o=1;o<8;o<<=1){
                    t0+=__shfl_xor_sync(0xffffffffu,t0,o);
                    t1+=__shfl_xor_sync(0xffffffffu,t1,o);
                }
                float p0=e0/t0,p1=e1/t1;
                SP[w*64+l]=p0; SP[w*64+32+l]=p1;
                size_t ab=(size_t)(b0+w)*1024+li*256+h*64;
                attn_out[ab+l]=p0; attn_out[ab+32+l]=p1;
                __syncwarp();
#pragma unroll
                for(int qq=0;qq<8;++qq){
                    float a0=0.f,a1=0.f;
#pragma unroll
                    for(int kk2=0;kk2<8;++kk2){
                        float p=SP[w*64+qq*8+kk2];
                        a0+=p*vB[kk2*64+l]; a1+=p*vB[kk2*64+32+l];
                    }
                    SCTX[(w*8+qq)*256+h*64+l]=a0;
                    SCTX[(w*8+qq)*256+h*64+32+l]=a1;
                }
            }
        }
        __syncthreads();
        cp_f4f(SW,Wo+li*16384,4096,tid);
        __syncthreads();
        gemm_blockF<256,256,false>(SCTX,SW,bo+li*64,ST,tid);
        __syncthreads();
        ln_blockF(ST,SX,g1+li*64,be1+li*64,w,l);
        __syncthreads();
        cp_f4f(SW,fW1+li*4096,1024,tid);
        cp_f4f(SW+4096,fW2+li*4096,1024,tid);
        __syncthreads();
        gemm_blockF<64,64,true>(SX,SW,fb1+li*64,ST+4096,tid);
        __syncthreads();
        gemm_blockF<64,64,false>(ST+4096,SW+4096,fb2+li*64,ST,tid);
        __syncthreads();
        ln_blockF(ST,SX,g2+li*64,be2+li*64,w,l);
    }

    for(int i=tid;i<512;i+=NTF)
        SQI[i]=query[(size_t)(b0+(i>>6))*64+(i&63)];

    for(int h=0;h<4;++h){
        __syncthreads();
        cp_slicef(SW,cWq+h*64,tid);
        cp_slicef(SW+4096,cWk+h*64,tid);
        cp_slicef(SW+8192,cWv+h*64,tid);
        __syncthreads();
        gemm_blockF<64,64,false>(SX,SW+4096,cbk+h*64,ST,tid);
        gemm_blockF<64,64,false>(SX,SW+8192,cbv+h*64,ST+4096,tid);
        for(int c=l;c<64;c+=32){
            float a=0.f;
#pragma unroll 8
            for(int k2=0;k2<64;++k2) a+=SQI[w*64+k2]*SW[k2*64+c];
            ST[8192+w*64+c]=a+cbq[h*64+c];
        }
        __syncthreads();
        {
            int j=l>>2,part=l&3;
            const float* qrow=ST+8192+w*64; const float* kB=ST+w*512;
            float sc=0.f;
#pragma unroll
            for(int d=part*16;d<part*16+16;++d) sc+=qrow[d]*kB[j*64+d];
            sc+=__shfl_xor_sync(0xffffffffu,sc,1);
            sc+=__shfl_xor_sync(0xffffffffu,sc,2);
            sc*=SC_ATT;
            if(part==0) SP[w*8+j]=sc;
            __syncwarp();
            float mx=-1e30f;
#pragma unroll
            for(int jj=0;jj<8;++jj) mx=fmaxf(mx,SP[w*8+jj]);
            float pe[8],ssum=0.f;
#pragma unroll
            for(int jj=0;jj<8;++jj){pe[jj]=expf(SP[w*8+jj]-mx);ssum+=pe[jj];}
            float inv=1.f/ssum;
            const float* vB=ST+4096+w*512;
            for(int c=l;c<64;c+=32){
                float a=0.f;
#pragma unroll
                for(int jj=0;jj<8;++jj) a+=pe[jj]*vB[jj*64+c];
                SCTX[(w*8)*256+h*64+c]=a*inv;
            }
        }
    }
    __syncthreads();
    cp_f4f(SW,cWo,4096,tid);
    __syncthreads();
    {
        const float* ctx=SCTX+w*2048;
        float a0=0.f,a1=0.f;
#pragma unroll 8
        for(int k2=0;k2<256;++k2){
            float cv=ctx[k2];
            a0+=cv*SW[k2*64+l]; a1+=cv*SW[k2*64+32+l];
        }
        a0=fmaxf(a0+cbo[l],0.f); a1=fmaxf(a1+cbo[l+32],0.f);
        SCA[w*64+l]=a0; SCA[w*64+32+l]=a1;
        __syncwarp();
#pragma unroll
        for(int cq=0;cq<3;++cq){
            float p=SCA[w*64+l]*Wc[l*3+cq]+SCA[w*64+32+l]*Wc[(l+32)*3+cq];
#pragma unroll
            for(int o=16;o>=1;o>>=1)p+=__shfl_xor_sync(0xffffffffu,p,o);
            if(l==0) out[(size_t)(b0+w)*3+cq]=p+bc[cq];
        }
        float m0=-1e30f,m1=-1e30f;
#pragma unroll
        for(int s2=0;s2<8;++s2){
            m0=fmaxf(m0,SX[(w*8+s2)*64+l]);
            m1=fmaxf(m1,SX[(w*8+s2)*64+32+l]);
        }
        float p=m0*Ws[l]+m1*Ws[l+32];
#pragma unroll
        for(int o=16;o>=1;o>>=1)p+=__shfl_xor_sync(0xffffffffu,p,o);
        if(l==0) out[OFF_SIGMA+b0+w]=p+bs[0];
    }
    for(int i=tid;i<4096;i+=NTF)
        out[OFF_OUT+(size_t)b0*512+i]=SX[i];
}

extern "C" void kernel_launch(void* const* d_in,const int* in_sizes,int n_in,
                              void* d_out,int out_size){
    (void)in_sizes;(void)n_in;(void)out_size;
    const float* query=(const float*)d_in[0];
    const float* latent=(const float*)d_in[1];
    const float* W1=(const float*)d_in[2];  const float* b1=(const float*)d_in[3];
    const float* Wq=(const float*)d_in[4];  const float* bq=(const float*)d_in[5];
    const float* Wk=(const float*)d_in[6];  const float* bk=(const float*)d_in[7];
    const float* Wv=(const float*)d_in[8];  const float* bv=(const float*)d_in[9];
    const float* Wo=(const float*)d_in[10]; const float* bo=(const float*)d_in[11];
    const float* fW1=(const float*)d_in[12];const float* fb1=(const float*)d_in[13];
    const float* fW2=(const float*)d_in[14];const float* fb2=(const float*)d_in[15];
    const float* g1=(const float*)d_in[16]; const float* be1=(const float*)d_in[17];
    const float* g2=(const float*)d_in[18]; const float* be2=(const float*)d_in[19];
    const float* cWq=(const float*)d_in[20];const float* cbq=(const float*)d_in[21];
    const float* cWk=(const float*)d_in[22];const float* cbk=(const float*)d_in[23];
    const float* cWv=(const float*)d_in[24];const float* cbv=(const float*)d_in[25];
    const float* cWo=(const float*)d_in[26];const float* cbo=(const float*)d_in[27];
    const float* Wc=(const float*)d_in[28]; const float* bc=(const float*)d_in[29];
    const float* Ws=(const float*)d_in[30]; const float* bs=(const float*)d_in[31];
    float* out=(float*)d_out;

    reset_kernel<<<1,1>>>();
    prep_kernel<<<(88*4096+255)/256,256>>>(W1,Wq,Wk,Wv,Wo,fW1,fW2,cWk,cWv);

    const int smem_mma=27664*sizeof(float);
    cudaFuncSetAttribute(radiance_mma,cudaFuncAttributeMaxDynamicSharedMemorySize,smem_mma);
    radiance_mma<<<MMA_GRID,512,smem_mma>>>(query,latent,b1,bq,bk,bv,bo,fb1,fb2,
        g1,be1,g2,be2,cWq,cbq,cbk,cbv,cWo,cbo,Wc,bc,Ws,bs,out);

    const int smem_ffma=F_SMEMF*sizeof(float);
    cudaFuncSetAttribute(radiance_ffma,cudaFuncAttributeMaxDynamicSharedMemorySize,smem_ffma);
    radiance_ffma<<<BB/8,256,smem_ffma>>>(query,latent,W1,b1,Wq,bq,Wk,bk,Wv,bv,Wo,bo,
        fW1,fb1,fW2,fb2,g1,be1,g2,be2,cWq,cbq,cWk,cbk,cWv,cbv,cWo,cbo,Wc,bc,Ws,bs,out);
}